// round 2
// baseline (speedup 1.0000x reference)
#include <cuda_runtime.h>
#include <float.h>

#define BN 8
#define NP 2048
#define KNB 40

__device__ __forceinline__ float lrelu(float v) { return v > 0.f ? v : 0.2f * v; }

// ------------------------- scratch (device globals) -------------------------
__device__ __align__(16) float g_xTa[BN * NP * 3];
__device__ __align__(16) float g_xTb[BN * NP * 3];
__device__ __align__(16) float g_xx[BN * NP];
__device__ __align__(16) int   g_idx[BN * NP * KNB];
__device__ __align__(16) float g_t128[BN * NP * 128];
__device__ __align__(16) float g_big[BN * 1024 * NP];
__device__ __align__(16) float g_cat[BN * NP * 192];
__device__ __align__(16) float g_vec[BN * 1088];
__device__ __align__(16) float g_t1024[BN * 1024];
__device__ __align__(16) float g_t512[BN * 512];
__device__ __align__(16) float g_t256[BN * 256];
__device__ __align__(16) float g_T9[BN * 9];
__device__ __align__(16) float g_bias[BN * 256];
__device__ __align__(16) float g_hA[BN * NP * 256];
__device__ __align__(16) float g_hB[BN * NP * 256];

// transposed-weight pool (floats)
#define OFF_tc1 0
#define OFF_tc2 (OFF_tc1 + 6*64)
#define OFF_tc3 (OFF_tc2 + 64*128)
#define OFF_b1a (OFF_tc3 + 128*1024)
#define OFF_b1b (OFF_b1a + 6*64)
#define OFF_b2a (OFF_b1b + 64*64)
#define OFF_b2b (OFF_b2a + 128*64)
#define OFF_b3a (OFF_b2b + 64*64)
#define OFF_m1  (OFF_b3a + 128*64)
#define OFF_h1p (OFF_m1  + 192*1024)
#define OFF_h2  (OFF_h1p + 192*256)
#define OFF_h3  (OFF_h2  + 256*256)
#define OFF_h4  (OFF_h3  + 256*128)
#define WT_TOTAL (OFF_h4 + 128*64)
__device__ __align__(16) float g_WT[WT_TOTAL];

// ------------------------- prep / small kernels -------------------------
__global__ void tw_kernel(const float* __restrict__ W, int O, int C, int ldW,
                          int coff, float* __restrict__ WT, int OCP) {
    int e = blockIdx.x * blockDim.x + threadIdx.x;
    if (e >= C * OCP) return;
    int c = e / OCP, o = e % OCP;
    WT[e] = (o < O) ? W[(size_t)o * ldW + coff + c] : 0.f;
}

__global__ void prep_kernel(const float* __restrict__ x, float* __restrict__ xT,
                            float* __restrict__ xx) {
    int b = blockIdx.y;
    int n = blockIdx.x * blockDim.x + threadIdx.x;
    float v0 = x[((size_t)b * 3 + 0) * NP + n];
    float v1 = x[((size_t)b * 3 + 1) * NP + n];
    float v2 = x[((size_t)b * 3 + 2) * NP + n];
    float* o = &xT[((size_t)b * NP + n) * 3];
    o[0] = v0; o[1] = v1; o[2] = v2;
    xx[b * NP + n] = v0 * v0 + v1 * v1 + v2 * v2;
}

__global__ void transform_kernel(const float* __restrict__ x, const float* __restrict__ T9,
                                 float* __restrict__ xT, float* __restrict__ xx) {
    int b = blockIdx.y;
    int n = blockIdx.x * blockDim.x + threadIdx.x;
    const float* T = &T9[b * 9];
    float v0 = x[((size_t)b * 3 + 0) * NP + n];
    float v1 = x[((size_t)b * 3 + 1) * NP + n];
    float v2 = x[((size_t)b * 3 + 2) * NP + n];
    float y0 = v0 * T[0] + v1 * T[3] + v2 * T[6];
    float y1 = v0 * T[1] + v1 * T[4] + v2 * T[7];
    float y2 = v0 * T[2] + v1 * T[5] + v2 * T[8];
    float* o = &xT[((size_t)b * NP + n) * 3];
    o[0] = y0; o[1] = y1; o[2] = y2;
    xx[b * NP + n] = y0 * y0 + y1 * y1 + y2 * y2;
}

__global__ void sumsq_kernel(const float* __restrict__ in, int ld, int coff, int C,
                             float* __restrict__ xx) {
    int i = blockIdx.x * blockDim.x + threadIdx.x;
    if (i >= BN * NP) return;
    const float* p = in + (size_t)i * ld + coff;
    float s = 0.f;
    for (int c = 0; c < C; c++) { float v = p[c]; s += v * v; }
    xx[i] = s;
}

// ------------------------- kNN -------------------------
template <int C>
__global__ void knn_kernel(const float* __restrict__ xT, int ld, int coff,
                           const float* __restrict__ xx, int* __restrict__ idx) {
    extern __shared__ float dist[];  // 8 * NP
    __shared__ float sctr[8][C];
    const int b = blockIdx.y, r0 = blockIdx.x * 8, tid = threadIdx.x;

    for (int e = tid; e < 8 * C; e += 256) {
        int r = e / C, c = e % C;
        sctr[r][c] = xT[((size_t)b * NP + r0 + r) * ld + coff + c];
    }
    __syncthreads();

    for (int j = tid; j < NP; j += 256) {
        const float* pj = xT + ((size_t)b * NP + j) * ld + coff;
        float acc[8];
#pragma unroll
        for (int r = 0; r < 8; r++) acc[r] = 0.f;
        for (int c = 0; c < C; c++) {
            float v = pj[c];
#pragma unroll
            for (int r = 0; r < 8; r++) acc[r] += v * sctr[r][c];
        }
        float xxj = xx[b * NP + j];
#pragma unroll
        for (int r = 0; r < 8; r++) dist[r * NP + j] = 2.f * acc[r] - xxj;
    }
    __syncthreads();

    const int w = tid >> 5, lane = tid & 31;
    float* dr = dist + w * NP;
    int* orow = idx + ((size_t)b * NP + r0 + w) * KNB;
    for (int k = 0; k < KNB; k++) {
        float bv = -FLT_MAX; int bi = -1;
        for (int j = lane; j < NP; j += 32) {
            float v = dr[j];
            if (v > bv) { bv = v; bi = j; }
        }
#pragma unroll
        for (int s = 16; s; s >>= 1) {
            float ov = __shfl_xor_sync(~0u, bv, s);
            int oi = __shfl_xor_sync(~0u, bi, s);
            if (ov > bv || (ov == bv && oi < bi)) { bv = ov; bi = oi; }
        }
        if (lane == 0) { orow[k] = bi; dr[bi] = -FLT_MAX; }
        __syncwarp();
    }
}

// ------------------------- fused edge-conv block -------------------------
template <int CIN, int CMID, int COUT, bool TWO>
__global__ void edge_kernel(const float* __restrict__ in, int ld, int coff,
                            const int* __restrict__ idx,
                            const float* __restrict__ W1T, const float* __restrict__ W2T,
                            float* __restrict__ out, int old, int ooff) {
    constexpr int FIN = 2 * CIN;
    constexpr int OC1 = TWO ? CMID : COUT;
    extern __shared__ float sm[];
    float* sW1 = sm;                               // FIN*OC1
    float* sW2 = sW1 + FIN * OC1;                  // TWO ? CMID*COUT : 0
    float* sf  = sW2 + (TWO ? CMID * COUT : 0);    // KNB*FIN
    float* sh  = sf + KNB * FIN;                   // TWO ? KNB*CMID : 0
    float* sv  = sh + (TWO ? KNB * CMID : 0);      // KNB*COUT
    __shared__ float sctr[CIN];
    __shared__ int sidx[KNB];

    const int b = blockIdx.y, n = blockIdx.x, tid = threadIdx.x;

    for (int e = tid; e < FIN * OC1; e += 256) sW1[e] = W1T[e];
    if (TWO) for (int e = tid; e < CMID * COUT; e += 256) sW2[e] = W2T[e];
    if (tid < CIN) sctr[tid] = in[((size_t)b * NP + n) * ld + coff + tid];
    if (tid < KNB) sidx[tid] = idx[((size_t)b * NP + n) * KNB + tid];
    __syncthreads();

    for (int e = tid; e < KNB * CIN; e += 256) {
        int k = e / CIN, c = e - k * CIN;
        float ctr = sctr[c];
        float nb = in[((size_t)b * NP + sidx[k]) * ld + coff + c];
        sf[k * FIN + c] = nb - ctr;
        sf[k * FIN + CIN + c] = ctr;
    }
    __syncthreads();

    {  // layer 1
        float* dst = TWO ? sh : sv;
        constexpr int TILES = (KNB / 2) * (OC1 / 4);
        for (int t = tid; t < TILES; t += 256) {
            int ot = t % (OC1 / 4), kt = t / (OC1 / 4);
            float a00=0,a01=0,a02=0,a03=0,a10=0,a11=0,a12=0,a13=0;
            const float* f0 = sf + (kt * 2) * FIN;
            const float* f1 = f0 + FIN;
#pragma unroll 4
            for (int c = 0; c < FIN; c++) {
                float4 w = *(const float4*)(sW1 + c * OC1 + ot * 4);
                float v0 = f0[c], v1 = f1[c];
                a00 += v0*w.x; a01 += v0*w.y; a02 += v0*w.z; a03 += v0*w.w;
                a10 += v1*w.x; a11 += v1*w.y; a12 += v1*w.z; a13 += v1*w.w;
            }
            float* d0 = dst + (kt * 2) * OC1 + ot * 4;
            float* d1 = d0 + OC1;
            d0[0]=lrelu(a00); d0[1]=lrelu(a01); d0[2]=lrelu(a02); d0[3]=lrelu(a03);
            d1[0]=lrelu(a10); d1[1]=lrelu(a11); d1[2]=lrelu(a12); d1[3]=lrelu(a13);
        }
    }
    __syncthreads();

    if (TWO) {  // layer 2
        constexpr int TILES = (KNB / 2) * (COUT / 4);
        for (int t = tid; t < TILES; t += 256) {
            int ot = t % (COUT / 4), kt = t / (COUT / 4);
            float a00=0,a01=0,a02=0,a03=0,a10=0,a11=0,a12=0,a13=0;
            const float* f0 = sh + (kt * 2) * CMID;
            const float* f1 = f0 + CMID;
#pragma unroll 4
            for (int c = 0; c < CMID; c++) {
                float4 w = *(const float4*)(sW2 + c * COUT + ot * 4);
                float v0 = f0[c], v1 = f1[c];
                a00 += v0*w.x; a01 += v0*w.y; a02 += v0*w.z; a03 += v0*w.w;
                a10 += v1*w.x; a11 += v1*w.y; a12 += v1*w.z; a13 += v1*w.w;
            }
            float* d0 = sv + (kt * 2) * COUT + ot * 4;
            float* d1 = d0 + COUT;
            d0[0]=lrelu(a00); d0[1]=lrelu(a01); d0[2]=lrelu(a02); d0[3]=lrelu(a03);
            d1[0]=lrelu(a10); d1[1]=lrelu(a11); d1[2]=lrelu(a12); d1[3]=lrelu(a13);
        }
        __syncthreads();
    }

    for (int o = tid; o < COUT; o += 256) {  // max over K
        float m = -FLT_MAX;
        for (int k = 0; k < KNB; k++) m = fmaxf(m, sv[k * COUT + o]);
        out[((size_t)b * NP + n) * old + ooff + o] = m;
    }
}

// ------------------------- tiled pointwise conv (SGEMM) -------------------------
__global__ void pconv_kernel(const float* __restrict__ in, int ld, int coff,
                             const float* __restrict__ WT, int CIN, int OCP,
                             const float* __restrict__ bias, int bstride,
                             float* __restrict__ out, int outCM, int old, int ooff,
                             int OC, int act) {
    __shared__ float sA[16][68];
    __shared__ float sB[16][64];
    const int b = blockIdx.z;
    const int n0 = blockIdx.x * 64, o0 = blockIdx.y * 64;
    const int tid = threadIdx.x;
    const int tx = tid % 16, ty = tid / 16;
    float acc[4][4] = {};

    for (int c0 = 0; c0 < CIN; c0 += 16) {
        {
            int p = tid >> 2, c4 = (tid & 3) * 4;
            const float* src = in + ((size_t)b * NP + n0 + p) * ld + coff + c0 + c4;
            float4 v = *(const float4*)src;
            sA[c4 + 0][p] = v.x; sA[c4 + 1][p] = v.y;
            sA[c4 + 2][p] = v.z; sA[c4 + 3][p] = v.w;
        }
        {
            int c = tid >> 4, o4 = (tid & 15) * 4;
            *(float4*)&sB[c][o4] = *(const float4*)(WT + (size_t)(c0 + c) * OCP + o0 + o4);
        }
        __syncthreads();
#pragma unroll
        for (int c = 0; c < 16; c++) {
            float4 av = *(const float4*)&sA[c][ty * 4];
            float4 bv = *(const float4*)&sB[c][tx * 4];
            acc[0][0]+=av.x*bv.x; acc[0][1]+=av.x*bv.y; acc[0][2]+=av.x*bv.z; acc[0][3]+=av.x*bv.w;
            acc[1][0]+=av.y*bv.x; acc[1][1]+=av.y*bv.y; acc[1][2]+=av.y*bv.z; acc[1][3]+=av.y*bv.w;
            acc[2][0]+=av.z*bv.x; acc[2][1]+=av.z*bv.y; acc[2][2]+=av.z*bv.z; acc[2][3]+=av.z*bv.w;
            acc[3][0]+=av.w*bv.x; acc[3][1]+=av.w*bv.y; acc[3][2]+=av.w*bv.z; acc[3][3]+=av.w*bv.w;
        }
        __syncthreads();
    }

#pragma unroll
    for (int i = 0; i < 4; i++) {
        int n = n0 + ty * 4 + i;
#pragma unroll
        for (int j = 0; j < 4; j++) {
            int o = o0 + tx * 4 + j;
            if (o >= OC) continue;
            float v = acc[i][j];
            if (bias) v += bias[b * bstride + o];
            if (act) v = lrelu(v);
            if (outCM) out[((size_t)b * OC + o) * NP + n] = v;
            else out[((size_t)b * NP + n) * old + ooff + o] = v;
        }
    }
}

__global__ void rowmax_kernel(const float* __restrict__ in, float* __restrict__ out,
                              int OC, int ostride, int ooff) {
    int row = blockIdx.x;
    int tid = threadIdx.x;
    float m = -FLT_MAX;
    for (int j = tid; j < NP; j += 256) m = fmaxf(m, in[(size_t)row * NP + j]);
    __shared__ float red[256];
    red[tid] = m; __syncthreads();
    for (int s = 128; s; s >>= 1) {
        if (tid < s) red[tid] = fmaxf(red[tid], red[tid + s]);
        __syncthreads();
    }
    if (tid == 0) {
        int b = row / OC, o = row % OC;
        out[b * ostride + ooff + o] = red[0];
    }
}

__global__ void fc_kernel(const float* __restrict__ in, int istride, int C,
                          const float* __restrict__ W, int wld, int O,
                          const float* __restrict__ bias, int bstride,
                          float* __restrict__ out, int ostride, int ooff, int act) {
    int b = blockIdx.x;
    int o = blockIdx.y * blockDim.x + threadIdx.x;
    if (o >= O) return;
    const float* ip = in + (size_t)b * istride;
    const float* wp = W + (size_t)o * wld;
    float s = 0.f;
    for (int c = 0; c < C; c++) s += ip[c] * wp[c];
    if (bias) s += bias[(size_t)b * bstride + o];
    if (act) s = lrelu(s);
    out[(size_t)b * ostride + ooff + o] = s;
}

// ------------------------- host -------------------------
extern "C" void kernel_launch(void* const* d_in, const int* in_sizes, int n_in,
                              void* d_out, int out_size) {
    const float* x    = (const float*)d_in[0];
    const float* l    = (const float*)d_in[1];
    const float* t_c1 = (const float*)d_in[2];
    const float* t_c2 = (const float*)d_in[3];
    const float* t_c3 = (const float*)d_in[4];
    const float* t_f1 = (const float*)d_in[5];
    const float* t_f2 = (const float*)d_in[6];
    const float* t_f3w= (const float*)d_in[7];
    const float* t_f3b= (const float*)d_in[8];
    const float* b1a  = (const float*)d_in[9];
    const float* b1b  = (const float*)d_in[10];
    const float* b2a  = (const float*)d_in[11];
    const float* b2b  = (const float*)d_in[12];
    const float* b3a  = (const float*)d_in[13];
    const float* m1   = (const float*)d_in[14];
    const float* m2   = (const float*)d_in[15];
    const float* h1   = (const float*)d_in[16];
    const float* h2   = (const float*)d_in[17];
    const float* h3   = (const float*)d_in[18];
    const float* h4   = (const float*)d_in[19];

    float *xTa, *xTb, *xx, *t128, *big, *cat, *vec, *t1024, *t512, *t256, *T9, *bsb, *hA, *hB, *WT;
    int* idxp;
    cudaGetSymbolAddress((void**)&xTa, g_xTa);
    cudaGetSymbolAddress((void**)&xTb, g_xTb);
    cudaGetSymbolAddress((void**)&xx, g_xx);
    cudaGetSymbolAddress((void**)&idxp, g_idx);
    cudaGetSymbolAddress((void**)&t128, g_t128);
    cudaGetSymbolAddress((void**)&big, g_big);
    cudaGetSymbolAddress((void**)&cat, g_cat);
    cudaGetSymbolAddress((void**)&vec, g_vec);
    cudaGetSymbolAddress((void**)&t1024, g_t1024);
    cudaGetSymbolAddress((void**)&t512, g_t512);
    cudaGetSymbolAddress((void**)&t256, g_t256);
    cudaGetSymbolAddress((void**)&T9, g_T9);
    cudaGetSymbolAddress((void**)&bsb, g_bias);
    cudaGetSymbolAddress((void**)&hA, g_hA);
    cudaGetSymbolAddress((void**)&hB, g_hB);
    cudaGetSymbolAddress((void**)&WT, g_WT);

    const int KNN_SMEM = 8 * NP * 4;                                     // 65536
    const int E1 = (6*64 + 64*128 + KNB*6 + KNB*64 + KNB*128) * 4;       // 65984
    const int E2 = (6*64 + 64*64 + KNB*6 + KNB*64 + KNB*64) * 4;         // 39360
    const int E3 = (128*64 + 64*64 + KNB*128 + KNB*64 + KNB*64) * 4;     // 90112
    const int E4 = (128*64 + KNB*128 + KNB*64) * 4;                      // 63488
    cudaFuncSetAttribute(knn_kernel<3>,  cudaFuncAttributeMaxDynamicSharedMemorySize, KNN_SMEM);
    cudaFuncSetAttribute(knn_kernel<64>, cudaFuncAttributeMaxDynamicSharedMemorySize, KNN_SMEM);
    cudaFuncSetAttribute(edge_kernel<3,64,128,true>,  cudaFuncAttributeMaxDynamicSharedMemorySize, E1);
    cudaFuncSetAttribute(edge_kernel<3,64,64,true>,   cudaFuncAttributeMaxDynamicSharedMemorySize, E2);
    cudaFuncSetAttribute(edge_kernel<64,64,64,true>,  cudaFuncAttributeMaxDynamicSharedMemorySize, E3);
    cudaFuncSetAttribute(edge_kernel<64,64,64,false>, cudaFuncAttributeMaxDynamicSharedMemorySize, E4);

    // weight transposes
    {
        struct TW { const float* W; int O, C, ldW, coff; int off, OCP; };
        TW tws[] = {
            {t_c1, 64, 6, 6, 0, OFF_tc1, 64},
            {t_c2, 128, 64, 64, 0, OFF_tc2, 128},
            {t_c3, 1024, 128, 128, 0, OFF_tc3, 1024},
            {b1a, 64, 6, 6, 0, OFF_b1a, 64},
            {b1b, 64, 64, 64, 0, OFF_b1b, 64},
            {b2a, 64, 128, 128, 0, OFF_b2a, 64},
            {b2b, 64, 64, 64, 0, OFF_b2b, 64},
            {b3a, 64, 128, 128, 0, OFF_b3a, 64},
            {m1, 1024, 192, 192, 0, OFF_m1, 1024},
            {h1, 256, 192, 1280, 1088, OFF_h1p, 256},
            {h2, 256, 256, 256, 0, OFF_h2, 256},
            {h3, 128, 256, 256, 0, OFF_h3, 128},
            {h4, 50, 128, 128, 0, OFF_h4, 64},
        };
        for (auto& t : tws) {
            int n = t.C * t.OCP;
            tw_kernel<<<(n + 255) / 256, 256>>>(t.W, t.O, t.C, t.ldW, t.coff, WT + t.off, t.OCP);
        }
    }

    // ---- transform net ----
    prep_kernel<<<dim3(NP / 256, BN), 256>>>(x, xTa, xx);
    knn_kernel<3><<<dim3(NP / 8, BN), 256, KNN_SMEM>>>(xTa, 3, 0, xx, idxp);
    edge_kernel<3,64,128,true><<<dim3(NP, BN), 256, E1>>>(
        xTa, 3, 0, idxp, WT + OFF_tc1, WT + OFF_tc2, t128, 128, 0);
    pconv_kernel<<<dim3(32, 16, BN), 256>>>(t128, 128, 0, WT + OFF_tc3, 128, 1024,
                                            nullptr, 0, big, 1, 0, 0, 1024, 1);
    rowmax_kernel<<<BN * 1024, 256>>>(big, t1024, 1024, 1024, 0);
    fc_kernel<<<dim3(BN, 2), 256>>>(t1024, 1024, 1024, t_f1, 1024, 512, nullptr, 0, t512, 512, 0, 1);
    fc_kernel<<<dim3(BN, 1), 256>>>(t512, 512, 512, t_f2, 512, 256, nullptr, 0, t256, 256, 0, 1);
    fc_kernel<<<dim3(BN, 1), 256>>>(t256, 256, 256, t_f3w, 256, 9, t_f3b, 0, T9, 9, 0, 0);
    transform_kernel<<<dim3(NP / 256, BN), 256>>>(x, T9, xTb, xx);

    // ---- edge blocks ----
    knn_kernel<3><<<dim3(NP / 8, BN), 256, KNN_SMEM>>>(xTb, 3, 0, xx, idxp);
    edge_kernel<3,64,64,true><<<dim3(NP, BN), 256, E2>>>(
        xTb, 3, 0, idxp, WT + OFF_b1a, WT + OFF_b1b, cat, 192, 0);

    sumsq_kernel<<<(BN * NP + 255) / 256, 256>>>(cat, 192, 0, 64, xx);
    knn_kernel<64><<<dim3(NP / 8, BN), 256, KNN_SMEM>>>(cat, 192, 0, xx, idxp);
    edge_kernel<64,64,64,true><<<dim3(NP, BN), 256, E3>>>(
        cat, 192, 0, idxp, WT + OFF_b2a, WT + OFF_b2b, cat, 192, 64);

    sumsq_kernel<<<(BN * NP + 255) / 256, 256>>>(cat, 192, 64, 64, xx);
    knn_kernel<64><<<dim3(NP / 8, BN), 256, KNN_SMEM>>>(cat, 192, 64, xx, idxp);
    edge_kernel<64,64,64,false><<<dim3(NP, BN), 256, E4>>>(
        cat, 192, 64, idxp, WT + OFF_b3a, nullptr, cat, 192, 128);

    // ---- global features ----
    pconv_kernel<<<dim3(32, 16, BN), 256>>>(cat, 192, 0, WT + OFF_m1, 192, 1024,
                                            nullptr, 0, big, 1, 0, 0, 1024, 1);
    rowmax_kernel<<<BN * 1024, 256>>>(big, vec, 1024, 1088, 0);
    fc_kernel<<<dim3(BN, 1), 256>>>(l, 16, 16, m2, 16, 64, nullptr, 0, vec, 1088, 1024, 1);
    fc_kernel<<<dim3(BN, 1), 256>>>(vec, 1088, 1088, h1, 1280, 256, nullptr, 0, bsb, 256, 0, 0);

    // ---- head ----
    pconv_kernel<<<dim3(32, 4, BN), 256>>>(cat, 192, 0, WT + OFF_h1p, 192, 256,
                                           bsb, 256, hA, 0, 256, 0, 256, 1);
    pconv_kernel<<<dim3(32, 4, BN), 256>>>(hA, 256, 0, WT + OFF_h2, 256, 256,
                                           nullptr, 0, hB, 0, 256, 0, 256, 1);
    pconv_kernel<<<dim3(32, 2, BN), 256>>>(hB, 256, 0, WT + OFF_h3, 256, 128,
                                           nullptr, 0, hA, 0, 128, 0, 128, 1);
    pconv_kernel<<<dim3(32, 1, BN), 256>>>(hA, 128, 0, WT + OFF_h4, 128, 64,
                                           nullptr, 0, (float*)d_out, 1, 0, 0, 50, 0);
}

// round 3
// speedup vs baseline: 1.0467x; 1.0467x over previous
#include <cuda_runtime.h>
#include <float.h>

#define BN 8
#define NP 2048
#define KNB 40

__device__ __forceinline__ float lrelu(float v) { return v > 0.f ? v : 0.2f * v; }

// ------------------------- scratch (device globals) -------------------------
__device__ __align__(16) float g_xTa[BN * NP * 3];
__device__ __align__(16) float g_xTb[BN * NP * 3];
__device__ __align__(16) float g_xx[BN * NP];
__device__ __align__(16) int   g_idx[BN * NP * KNB];
__device__ __align__(16) float g_t128[BN * NP * 128];
__device__ __align__(16) float g_big[BN * 1024 * NP];
__device__ __align__(16) float g_cat[BN * NP * 192];
__device__ __align__(16) float g_vec[BN * 1088];
__device__ __align__(16) float g_t1024[BN * 1024];
__device__ __align__(16) float g_t512[BN * 512];
__device__ __align__(16) float g_t256[BN * 256];
__device__ __align__(16) float g_T9[BN * 9];
__device__ __align__(16) float g_bias[BN * 256];
__device__ __align__(16) float g_hA[BN * NP * 256];
__device__ __align__(16) float g_hB[BN * NP * 256];

// transposed-weight pool (floats)
#define OFF_tc1 0
#define OFF_tc2 (OFF_tc1 + 6*64)
#define OFF_tc3 (OFF_tc2 + 64*128)
#define OFF_b1a (OFF_tc3 + 128*1024)
#define OFF_b1b (OFF_b1a + 6*64)
#define OFF_b2a (OFF_b1b + 64*64)
#define OFF_b2b (OFF_b2a + 128*64)
#define OFF_b3a (OFF_b2b + 64*64)
#define OFF_m1  (OFF_b3a + 128*64)
#define OFF_h1p (OFF_m1  + 192*1024)
#define OFF_h2  (OFF_h1p + 192*256)
#define OFF_h3  (OFF_h2  + 256*256)
#define OFF_h4  (OFF_h3  + 256*128)
#define WT_TOTAL (OFF_h4 + 128*64)
__device__ __align__(16) float g_WT[WT_TOTAL];

// ------------------------- prep / small kernels -------------------------
__global__ void tw_kernel(const float* __restrict__ W, int O, int C, int ldW,
                          int coff, float* __restrict__ WT, int OCP) {
    int e = blockIdx.x * blockDim.x + threadIdx.x;
    if (e >= C * OCP) return;
    int c = e / OCP, o = e % OCP;
    WT[e] = (o < O) ? W[(size_t)o * ldW + coff + c] : 0.f;
}

__global__ void prep_kernel(const float* __restrict__ x, float* __restrict__ xT,
                            float* __restrict__ xx) {
    int b = blockIdx.y;
    int n = blockIdx.x * blockDim.x + threadIdx.x;
    float v0 = x[((size_t)b * 3 + 0) * NP + n];
    float v1 = x[((size_t)b * 3 + 1) * NP + n];
    float v2 = x[((size_t)b * 3 + 2) * NP + n];
    float* o = &xT[((size_t)b * NP + n) * 3];
    o[0] = v0; o[1] = v1; o[2] = v2;
    xx[b * NP + n] = v0 * v0 + v1 * v1 + v2 * v2;
}

__global__ void transform_kernel(const float* __restrict__ x, const float* __restrict__ T9,
                                 float* __restrict__ xT, float* __restrict__ xx) {
    int b = blockIdx.y;
    int n = blockIdx.x * blockDim.x + threadIdx.x;
    const float* T = &T9[b * 9];
    float v0 = x[((size_t)b * 3 + 0) * NP + n];
    float v1 = x[((size_t)b * 3 + 1) * NP + n];
    float v2 = x[((size_t)b * 3 + 2) * NP + n];
    float y0 = v0 * T[0] + v1 * T[3] + v2 * T[6];
    float y1 = v0 * T[1] + v1 * T[4] + v2 * T[7];
    float y2 = v0 * T[2] + v1 * T[5] + v2 * T[8];
    float* o = &xT[((size_t)b * NP + n) * 3];
    o[0] = y0; o[1] = y1; o[2] = y2;
    xx[b * NP + n] = y0 * y0 + y1 * y1 + y2 * y2;
}

__global__ void sumsq_kernel(const float* __restrict__ in, int ld, int coff, int C,
                             float* __restrict__ xx) {
    int i = blockIdx.x * blockDim.x + threadIdx.x;
    if (i >= BN * NP) return;
    const float* p = in + (size_t)i * ld + coff;
    float s = 0.f;
    for (int c = 0; c < C; c++) { float v = p[c]; s += v * v; }
    xx[i] = s;
}

// ------------------------- kNN -------------------------
template <int C>
__global__ void knn_kernel(const float* __restrict__ xT, int ld, int coff,
                           const float* __restrict__ xx, int* __restrict__ idx) {
    extern __shared__ float dist[];  // 8 * NP
    __shared__ float sctr[8][C];
    const int b = blockIdx.y, r0 = blockIdx.x * 8, tid = threadIdx.x;

    for (int e = tid; e < 8 * C; e += 256) {
        int r = e / C, c = e % C;
        sctr[r][c] = xT[((size_t)b * NP + r0 + r) * ld + coff + c];
    }
    __syncthreads();

    for (int j = tid; j < NP; j += 256) {
        const float* pj = xT + ((size_t)b * NP + j) * ld + coff;
        float acc[8];
#pragma unroll
        for (int r = 0; r < 8; r++) acc[r] = 0.f;
        for (int c = 0; c < C; c++) {
            float v = pj[c];
#pragma unroll
            for (int r = 0; r < 8; r++) acc[r] += v * sctr[r][c];
        }
        float xxj = xx[b * NP + j];
#pragma unroll
        for (int r = 0; r < 8; r++) dist[r * NP + j] = 2.f * acc[r] - xxj;
    }
    __syncthreads();

    const int w = tid >> 5, lane = tid & 31;
    float* dr = dist + w * NP;
    int* orow = idx + ((size_t)b * NP + r0 + w) * KNB;
    for (int k = 0; k < KNB; k++) {
        float bv = -FLT_MAX; int bi = -1;
        for (int j = lane; j < NP; j += 32) {
            float v = dr[j];
            if (v > bv) { bv = v; bi = j; }
        }
#pragma unroll
        for (int s = 16; s; s >>= 1) {
            float ov = __shfl_xor_sync(~0u, bv, s);
            int oi = __shfl_xor_sync(~0u, bi, s);
            if (ov > bv || (ov == bv && oi < bi)) { bv = ov; bi = oi; }
        }
        if (lane == 0) { orow[k] = bi; dr[bi] = -FLT_MAX; }
        __syncwarp();
    }
}

// ------------------------- fused edge-conv block (v2: 4x4 tiles, T-layout) ---
// Layer GEMM over A (c-major: [Cin][KNB]) x W ([Cin][OC]) -> D (k-major: [KNB][OC])
// Second layer reads its A k-major ([KNB][Cin]) via scalar broadcast loads.
template <int CIN, int CMID, int COUT, bool TWO>
__global__ void edge_kernel(const float* __restrict__ in, int ld, int coff,
                            const int* __restrict__ idx,
                            const float* __restrict__ W1T, const float* __restrict__ W2T,
                            float* __restrict__ out, int old, int ooff) {
    constexpr int FIN = 2 * CIN;
    constexpr int OC1 = TWO ? CMID : COUT;
    constexpr int NT = 160;
    extern __shared__ float sm[];
    float* sW1 = sm;                                   // FIN*OC1
    float* sW2 = sW1 + FIN * OC1;                      // TWO ? CMID*COUT : 0
    float* sA  = sW2 + (TWO ? CMID * COUT : 0);        // FIN*KNB (c-major)
    float* sH  = sA + FIN * KNB;                       // TWO ? KNB*CMID : 0 (k-major)
    float* sO  = sH + (TWO ? KNB * CMID : 0);          // KNB*COUT (k-major)
    __shared__ float sctr[CIN];
    __shared__ int sidx[KNB];

    const int b = blockIdx.y, n = blockIdx.x, tid = threadIdx.x;

    for (int e = tid; e < FIN * OC1; e += NT) sW1[e] = W1T[e];
    if (TWO) for (int e = tid; e < CMID * COUT; e += NT) sW2[e] = W2T[e];
    if (tid < CIN) sctr[tid] = in[((size_t)b * NP + n) * ld + coff + tid];
    if (tid < KNB) sidx[tid] = idx[((size_t)b * NP + n) * KNB + tid];
    __syncthreads();

    // gather, k-fast (conflict-free STS), c-major storage
    for (int e = tid; e < KNB * CIN; e += NT) {
        int k = e % KNB, c = e / KNB;
        float ctr = sctr[c];
        float nb = in[((size_t)b * NP + sidx[k]) * ld + coff + c];
        sA[c * KNB + k] = nb - ctr;
        sA[(CIN + c) * KNB + k] = ctr;
    }
    __syncthreads();

    {  // layer 1: A c-major (float4 over k), W float4 over o; out k-major
        float* dst = TWO ? sH : sO;
        constexpr int OT = OC1 / 4;
        constexpr int TILES = (KNB / 4) * OT;
        for (int t = tid; t < TILES; t += NT) {
            int kt = t / OT, ot = t % OT;
            float acc[4][4] = {};  // [kj][oi]
#pragma unroll 2
            for (int c = 0; c < FIN; c++) {
                float4 a = *(const float4*)(sA + c * KNB + kt * 4);
                float4 w = *(const float4*)(sW1 + c * OC1 + ot * 4);
                acc[0][0]+=a.x*w.x; acc[0][1]+=a.x*w.y; acc[0][2]+=a.x*w.z; acc[0][3]+=a.x*w.w;
                acc[1][0]+=a.y*w.x; acc[1][1]+=a.y*w.y; acc[1][2]+=a.y*w.z; acc[1][3]+=a.y*w.w;
                acc[2][0]+=a.z*w.x; acc[2][1]+=a.z*w.y; acc[2][2]+=a.z*w.z; acc[2][3]+=a.z*w.w;
                acc[3][0]+=a.w*w.x; acc[3][1]+=a.w*w.y; acc[3][2]+=a.w*w.z; acc[3][3]+=a.w*w.w;
            }
#pragma unroll
            for (int kj = 0; kj < 4; kj++)
#pragma unroll
                for (int oi = 0; oi < 4; oi++)
                    dst[(kt * 4 + kj) * OC1 + ot * 4 + oi] = lrelu(acc[kj][oi]);
        }
    }
    __syncthreads();

    if (TWO) {  // layer 2: A k-major (scalar broadcast), W float4; out k-major
        constexpr int OT = COUT / 4;
        constexpr int TILES = (KNB / 4) * OT;
        for (int t = tid; t < TILES; t += NT) {
            int kt = t / OT, ot = t % OT;
            float acc[4][4] = {};
            const float* a0 = sH + (kt * 4 + 0) * CMID;
            const float* a1 = a0 + CMID;
            const float* a2 = a1 + CMID;
            const float* a3 = a2 + CMID;
#pragma unroll 4
            for (int c = 0; c < CMID; c++) {
                float4 w = *(const float4*)(sW2 + c * COUT + ot * 4);
                float v0 = a0[c], v1 = a1[c], v2 = a2[c], v3 = a3[c];
                acc[0][0]+=v0*w.x; acc[0][1]+=v0*w.y; acc[0][2]+=v0*w.z; acc[0][3]+=v0*w.w;
                acc[1][0]+=v1*w.x; acc[1][1]+=v1*w.y; acc[1][2]+=v1*w.z; acc[1][3]+=v1*w.w;
                acc[2][0]+=v2*w.x; acc[2][1]+=v2*w.y; acc[2][2]+=v2*w.z; acc[2][3]+=v2*w.w;
                acc[3][0]+=v3*w.x; acc[3][1]+=v3*w.y; acc[3][2]+=v3*w.z; acc[3][3]+=v3*w.w;
            }
#pragma unroll
            for (int kj = 0; kj < 4; kj++)
#pragma unroll
                for (int oi = 0; oi < 4; oi++)
                    sO[(kt * 4 + kj) * COUT + ot * 4 + oi] = lrelu(acc[kj][oi]);
        }
        __syncthreads();
    }

    // max over K: column-contiguous reads, conflict-free
    for (int o = tid; o < COUT; o += NT) {
        float m = -FLT_MAX;
#pragma unroll 8
        for (int k = 0; k < KNB; k++) m = fmaxf(m, sO[k * COUT + o]);
        out[((size_t)b * NP + n) * old + ooff + o] = m;
    }
}

// ------------------------- tiled pointwise conv (SGEMM) -------------------------
__global__ void pconv_kernel(const float* __restrict__ in, int ld, int coff,
                             const float* __restrict__ WT, int CIN, int OCP,
                             const float* __restrict__ bias, int bstride,
                             float* __restrict__ out, int outCM, int old, int ooff,
                             int OC, int act) {
    __shared__ float sA[16][68];
    __shared__ float sB[16][64];
    const int b = blockIdx.z;
    const int n0 = blockIdx.x * 64, o0 = blockIdx.y * 64;
    const int tid = threadIdx.x;
    const int tx = tid % 16, ty = tid / 16;
    float acc[4][4] = {};

    for (int c0 = 0; c0 < CIN; c0 += 16) {
        {
            int p = tid >> 2, c4 = (tid & 3) * 4;
            const float* src = in + ((size_t)b * NP + n0 + p) * ld + coff + c0 + c4;
            float4 v = *(const float4*)src;
            sA[c4 + 0][p] = v.x; sA[c4 + 1][p] = v.y;
            sA[c4 + 2][p] = v.z; sA[c4 + 3][p] = v.w;
        }
        {
            int c = tid >> 4, o4 = (tid & 15) * 4;
            *(float4*)&sB[c][o4] = *(const float4*)(WT + (size_t)(c0 + c) * OCP + o0 + o4);
        }
        __syncthreads();
#pragma unroll
        for (int c = 0; c < 16; c++) {
            float4 av = *(const float4*)&sA[c][ty * 4];
            float4 bv = *(const float4*)&sB[c][tx * 4];
            acc[0][0]+=av.x*bv.x; acc[0][1]+=av.x*bv.y; acc[0][2]+=av.x*bv.z; acc[0][3]+=av.x*bv.w;
            acc[1][0]+=av.y*bv.x; acc[1][1]+=av.y*bv.y; acc[1][2]+=av.y*bv.z; acc[1][3]+=av.y*bv.w;
            acc[2][0]+=av.z*bv.x; acc[2][1]+=av.z*bv.y; acc[2][2]+=av.z*bv.z; acc[2][3]+=av.z*bv.w;
            acc[3][0]+=av.w*bv.x; acc[3][1]+=av.w*bv.y; acc[3][2]+=av.w*bv.z; acc[3][3]+=av.w*bv.w;
        }
        __syncthreads();
    }

#pragma unroll
    for (int i = 0; i < 4; i++) {
        int n = n0 + ty * 4 + i;
#pragma unroll
        for (int j = 0; j < 4; j++) {
            int o = o0 + tx * 4 + j;
            if (o >= OC) continue;
            float v = acc[i][j];
            if (bias) v += bias[b * bstride + o];
            if (act) v = lrelu(v);
            if (outCM) out[((size_t)b * OC + o) * NP + n] = v;
            else out[((size_t)b * NP + n) * old + ooff + o] = v;
        }
    }
}

__global__ void rowmax_kernel(const float* __restrict__ in, float* __restrict__ out,
                              int OC, int ostride, int ooff) {
    int row = blockIdx.x;
    int tid = threadIdx.x;
    float m = -FLT_MAX;
    for (int j = tid; j < NP; j += 256) m = fmaxf(m, in[(size_t)row * NP + j]);
    __shared__ float red[256];
    red[tid] = m; __syncthreads();
    for (int s = 128; s; s >>= 1) {
        if (tid < s) red[tid] = fmaxf(red[tid], red[tid + s]);
        __syncthreads();
    }
    if (tid == 0) {
        int b = row / OC, o = row % OC;
        out[b * ostride + ooff + o] = red[0];
    }
}

__global__ void fc_kernel(const float* __restrict__ in, int istride, int C,
                          const float* __restrict__ W, int wld, int O,
                          const float* __restrict__ bias, int bstride,
                          float* __restrict__ out, int ostride, int ooff, int act) {
    int b = blockIdx.x;
    int o = blockIdx.y * blockDim.x + threadIdx.x;
    if (o >= O) return;
    const float* ip = in + (size_t)b * istride;
    const float* wp = W + (size_t)o * wld;
    float s = 0.f;
    for (int c = 0; c < C; c++) s += ip[c] * wp[c];
    if (bias) s += bias[(size_t)b * bstride + o];
    if (act) s = lrelu(s);
    out[(size_t)b * ostride + ooff + o] = s;
}

// ------------------------- host -------------------------
extern "C" void kernel_launch(void* const* d_in, const int* in_sizes, int n_in,
                              void* d_out, int out_size) {
    const float* x    = (const float*)d_in[0];
    const float* l    = (const float*)d_in[1];
    const float* t_c1 = (const float*)d_in[2];
    const float* t_c2 = (const float*)d_in[3];
    const float* t_c3 = (const float*)d_in[4];
    const float* t_f1 = (const float*)d_in[5];
    const float* t_f2 = (const float*)d_in[6];
    const float* t_f3w= (const float*)d_in[7];
    const float* t_f3b= (const float*)d_in[8];
    const float* b1a  = (const float*)d_in[9];
    const float* b1b  = (const float*)d_in[10];
    const float* b2a  = (const float*)d_in[11];
    const float* b2b  = (const float*)d_in[12];
    const float* b3a  = (const float*)d_in[13];
    const float* m1   = (const float*)d_in[14];
    const float* m2   = (const float*)d_in[15];
    const float* h1   = (const float*)d_in[16];
    const float* h2   = (const float*)d_in[17];
    const float* h3   = (const float*)d_in[18];
    const float* h4   = (const float*)d_in[19];

    float *xTa, *xTb, *xx, *t128, *big, *cat, *vec, *t1024, *t512, *t256, *T9, *bsb, *hA, *hB, *WT;
    int* idxp;
    cudaGetSymbolAddress((void**)&xTa, g_xTa);
    cudaGetSymbolAddress((void**)&xTb, g_xTb);
    cudaGetSymbolAddress((void**)&xx, g_xx);
    cudaGetSymbolAddress((void**)&idxp, g_idx);
    cudaGetSymbolAddress((void**)&t128, g_t128);
    cudaGetSymbolAddress((void**)&big, g_big);
    cudaGetSymbolAddress((void**)&cat, g_cat);
    cudaGetSymbolAddress((void**)&vec, g_vec);
    cudaGetSymbolAddress((void**)&t1024, g_t1024);
    cudaGetSymbolAddress((void**)&t512, g_t512);
    cudaGetSymbolAddress((void**)&t256, g_t256);
    cudaGetSymbolAddress((void**)&T9, g_T9);
    cudaGetSymbolAddress((void**)&bsb, g_bias);
    cudaGetSymbolAddress((void**)&hA, g_hA);
    cudaGetSymbolAddress((void**)&hB, g_hB);
    cudaGetSymbolAddress((void**)&WT, g_WT);

    const int KNN_SMEM = 8 * NP * 4;                                     // 65536
    const int E1 = (6*64 + 64*128 + KNB*6 + KNB*64 + KNB*128) * 4;       // 65984
    const int E2 = (6*64 + 64*64 + KNB*6 + KNB*64 + KNB*64) * 4;         // 39360
    const int E3 = (128*64 + 64*64 + KNB*128 + KNB*64 + KNB*64) * 4;     // 90112
    const int E4 = (128*64 + KNB*128 + KNB*64) * 4;                      // 63488
    cudaFuncSetAttribute(knn_kernel<3>,  cudaFuncAttributeMaxDynamicSharedMemorySize, KNN_SMEM);
    cudaFuncSetAttribute(knn_kernel<64>, cudaFuncAttributeMaxDynamicSharedMemorySize, KNN_SMEM);
    cudaFuncSetAttribute(edge_kernel<3,64,128,true>,  cudaFuncAttributeMaxDynamicSharedMemorySize, E1);
    cudaFuncSetAttribute(edge_kernel<3,64,64,true>,   cudaFuncAttributeMaxDynamicSharedMemorySize, E2);
    cudaFuncSetAttribute(edge_kernel<64,64,64,true>,  cudaFuncAttributeMaxDynamicSharedMemorySize, E3);
    cudaFuncSetAttribute(edge_kernel<64,64,64,false>, cudaFuncAttributeMaxDynamicSharedMemorySize, E4);

    // --- weight transposes needed before edge E1 (3 launches so ncu -s 5 hits edge E1) ---
    tw_kernel<<<(6*64 + 255) / 256, 256>>>(t_c1, 64, 6, 6, 0, WT + OFF_tc1, 64);          // launch 0
    tw_kernel<<<(64*128 + 255) / 256, 256>>>(t_c2, 128, 64, 64, 0, WT + OFF_tc2, 128);    // launch 1
    tw_kernel<<<(128*1024 + 255) / 256, 256>>>(t_c3, 1024, 128, 128, 0, WT + OFF_tc3, 1024); // launch 2

    // ---- transform net ----
    prep_kernel<<<dim3(NP / 256, BN), 256>>>(x, xTa, xx);                                 // launch 3
    knn_kernel<3><<<dim3(NP / 8, BN), 256, KNN_SMEM>>>(xTa, 3, 0, xx, idxp);              // launch 4
    edge_kernel<3,64,128,true><<<dim3(NP, BN), 160, E1>>>(
        xTa, 3, 0, idxp, WT + OFF_tc1, WT + OFF_tc2, t128, 128, 0);                       // launch 5 (profiled)

    // remaining weight transposes
    {
        struct TW { const float* W; int O, C, ldW, coff; int off, OCP; };
        TW tws[] = {
            {b1a, 64, 6, 6, 0, OFF_b1a, 64},
            {b1b, 64, 64, 64, 0, OFF_b1b, 64},
            {b2a, 64, 128, 128, 0, OFF_b2a, 64},
            {b2b, 64, 64, 64, 0, OFF_b2b, 64},
            {b3a, 64, 128, 128, 0, OFF_b3a, 64},
            {m1, 1024, 192, 192, 0, OFF_m1, 1024},
            {h1, 256, 192, 1280, 1088, OFF_h1p, 256},
            {h2, 256, 256, 256, 0, OFF_h2, 256},
            {h3, 128, 256, 256, 0, OFF_h3, 128},
            {h4, 50, 128, 128, 0, OFF_h4, 64},
        };
        for (auto& t : tws) {
            int n = t.C * t.OCP;
            tw_kernel<<<(n + 255) / 256, 256>>>(t.W, t.O, t.C, t.ldW, t.coff, WT + t.off, t.OCP);
        }
    }

    pconv_kernel<<<dim3(32, 16, BN), 256>>>(t128, 128, 0, WT + OFF_tc3, 128, 1024,
                                            nullptr, 0, big, 1, 0, 0, 1024, 1);
    rowmax_kernel<<<BN * 1024, 256>>>(big, t1024, 1024, 1024, 0);
    fc_kernel<<<dim3(BN, 2), 256>>>(t1024, 1024, 1024, t_f1, 1024, 512, nullptr, 0, t512, 512, 0, 1);
    fc_kernel<<<dim3(BN, 1), 256>>>(t512, 512, 512, t_f2, 512, 256, nullptr, 0, t256, 256, 0, 1);
    fc_kernel<<<dim3(BN, 1), 256>>>(t256, 256, 256, t_f3w, 256, 9, t_f3b, 0, T9, 9, 0, 0);
    transform_kernel<<<dim3(NP / 256, BN), 256>>>(x, T9, xTb, xx);

    // ---- edge blocks ----
    knn_kernel<3><<<dim3(NP / 8, BN), 256, KNN_SMEM>>>(xTb, 3, 0, xx, idxp);
    edge_kernel<3,64,64,true><<<dim3(NP, BN), 160, E2>>>(
        xTb, 3, 0, idxp, WT + OFF_b1a, WT + OFF_b1b, cat, 192, 0);

    sumsq_kernel<<<(BN * NP + 255) / 256, 256>>>(cat, 192, 0, 64, xx);
    knn_kernel<64><<<dim3(NP / 8, BN), 256, KNN_SMEM>>>(cat, 192, 0, xx, idxp);
    edge_kernel<64,64,64,true><<<dim3(NP, BN), 160, E3>>>(
        cat, 192, 0, idxp, WT + OFF_b2a, WT + OFF_b2b, cat, 192, 64);

    sumsq_kernel<<<(BN * NP + 255) / 256, 256>>>(cat, 192, 64, 64, xx);
    knn_kernel<64><<<dim3(NP / 8, BN), 256, KNN_SMEM>>>(cat, 192, 64, xx, idxp);
    edge_kernel<64,64,64,false><<<dim3(NP, BN), 160, E4>>>(
        cat, 192, 64, idxp, WT + OFF_b3a, nullptr, cat, 192, 128);

    // ---- global features ----
    pconv_kernel<<<dim3(32, 16, BN), 256>>>(cat, 192, 0, WT + OFF_m1, 192, 1024,
                                            nullptr, 0, big, 1, 0, 0, 1024, 1);
    rowmax_kernel<<<BN * 1024, 256>>>(big, vec, 1024, 1088, 0);
    fc_kernel<<<dim3(BN, 1), 256>>>(l, 16, 16, m2, 16, 64, nullptr, 0, vec, 1088, 1024, 1);
    fc_kernel<<<dim3(BN, 1), 256>>>(vec, 1088, 1088, h1, 1280, 256, nullptr, 0, bsb, 256, 0, 0);

    // ---- head ----
    pconv_kernel<<<dim3(32, 4, BN), 256>>>(cat, 192, 0, WT + OFF_h1p, 192, 256,
                                           bsb, 256, hA, 0, 256, 0, 256, 1);
    pconv_kernel<<<dim3(32, 4, BN), 256>>>(hA, 256, 0, WT + OFF_h2, 256, 256,
                                           nullptr, 0, hB, 0, 256, 0, 256, 1);
    pconv_kernel<<<dim3(32, 2, BN), 256>>>(hB, 256, 0, WT + OFF_h3, 256, 128,
                                           nullptr, 0, hA, 0, 128, 0, 128, 1);
    pconv_kernel<<<dim3(32, 1, BN), 256>>>(hA, 128, 0, WT + OFF_h4, 128, 64,
                                           nullptr, 0, (float*)d_out, 1, 0, 0, 50, 0);
}

// round 5
// speedup vs baseline: 1.9510x; 1.8640x over previous
#include <cuda_runtime.h>
#include <float.h>

#define BN 8
#define NP 2048
#define KNB 40

__device__ __forceinline__ float lrelu(float v) { return v > 0.f ? v : 0.2f * v; }

// ------------------------- scratch (device globals) -------------------------
__device__ __align__(16) float g_xTa[BN * NP * 3];
__device__ __align__(16) float g_xTb[BN * NP * 3];
__device__ __align__(16) float g_xx[BN * NP];
__device__ __align__(16) int   g_idx[BN * NP * KNB];
__device__ __align__(16) float g_t128[BN * NP * 128];
__device__ __align__(16) float g_PQ[BN * NP * 128];
__device__ __align__(16) float g_xC[BN * 64 * NP];
__device__ __align__(16) float g_pm[32 * BN * 1024];
__device__ __align__(16) float g_cat[BN * NP * 192];
__device__ __align__(16) float g_vec[BN * 1088];
__device__ __align__(16) float g_t1024[BN * 1024];
__device__ __align__(16) float g_t512[BN * 512];
__device__ __align__(16) float g_t256[BN * 256];
__device__ __align__(16) float g_T9[BN * 9];
__device__ __align__(16) float g_bias[BN * 256];
__device__ __align__(16) float g_hA[BN * NP * 256];
__device__ __align__(16) float g_hB[BN * NP * 256];

// transposed-weight pool
#define OFF_tc2 0
#define OFF_tc3 (OFF_tc2 + 64*128)
#define OFF_b1b (OFF_tc3 + 128*1024)
#define OFF_b2b (OFF_b1b + 64*64)
#define OFF_m1  (OFF_b2b + 64*64)
#define OFF_h1p (OFF_m1  + 192*1024)
#define OFF_h2  (OFF_h1p + 192*256)
#define OFF_h3  (OFF_h2  + 256*256)
#define OFF_h4  (OFF_h3  + 256*128)
#define OFF_pq2 (OFF_h4  + 128*64)
#define OFF_pq3 (OFF_pq2 + 64*128)
#define WT_TOTAL (OFF_pq3 + 64*128)
__device__ __align__(16) float g_WT[WT_TOTAL];

// ------------------------- prep / small kernels -------------------------
__global__ void tw_kernel(const float* __restrict__ W, int O, int C, int ldW,
                          int coff, float* __restrict__ WT, int OCP) {
    int e = blockIdx.x * blockDim.x + threadIdx.x;
    if (e >= C * OCP) return;
    int c = e / OCP, o = e % OCP;
    WT[e] = (o < O) ? W[(size_t)o * ldW + coff + c] : 0.f;
}

// PQ weight: cols [0,64) = Wa^T, [64,128) = (Wb - Wa)^T.  W: (64, 2*CIN) row-major
__global__ void tw2_kernel(const float* __restrict__ W, int CIN, float* __restrict__ WT) {
    int e = blockIdx.x * blockDim.x + threadIdx.x;
    if (e >= CIN * 128) return;
    int c = e / 128, o = e % 128;
    if (o < 64) WT[e] = W[(size_t)o * 2 * CIN + c];
    else {
        int oo = o - 64;
        WT[e] = W[(size_t)oo * 2 * CIN + CIN + c] - W[(size_t)oo * 2 * CIN + c];
    }
}

__global__ void prep_kernel(const float* __restrict__ x, float* __restrict__ xT,
                            float* __restrict__ xx) {
    int b = blockIdx.y;
    int n = blockIdx.x * blockDim.x + threadIdx.x;
    float v0 = x[((size_t)b * 3 + 0) * NP + n];
    float v1 = x[((size_t)b * 3 + 1) * NP + n];
    float v2 = x[((size_t)b * 3 + 2) * NP + n];
    float* o = &xT[((size_t)b * NP + n) * 3];
    o[0] = v0; o[1] = v1; o[2] = v2;
    xx[b * NP + n] = v0 * v0 + v1 * v1 + v2 * v2;
}

__global__ void transform_kernel(const float* __restrict__ x, const float* __restrict__ T9,
                                 float* __restrict__ xT, float* __restrict__ xx) {
    int b = blockIdx.y;
    int n = blockIdx.x * blockDim.x + threadIdx.x;
    const float* T = &T9[b * 9];
    float v0 = x[((size_t)b * 3 + 0) * NP + n];
    float v1 = x[((size_t)b * 3 + 1) * NP + n];
    float v2 = x[((size_t)b * 3 + 2) * NP + n];
    float y0 = v0 * T[0] + v1 * T[3] + v2 * T[6];
    float y1 = v0 * T[1] + v1 * T[4] + v2 * T[7];
    float y2 = v0 * T[2] + v1 * T[5] + v2 * T[8];
    float* o = &xT[((size_t)b * NP + n) * 3];
    o[0] = y0; o[1] = y1; o[2] = y2;
    xx[b * NP + n] = y0 * y0 + y1 * y1 + y2 * y2;
}

// P|Q for CIN=3 layers: out[n] = [Wa@x_n (64) | (Wb-Wa)@x_n (64)]
__global__ void pq3_kernel(const float* __restrict__ xT, const float* __restrict__ W,
                           float* __restrict__ PQ) {
    __shared__ float sw[128 * 3];
    int b = blockIdx.y;
    int n = blockIdx.x * blockDim.x + threadIdx.x;
    int tid = threadIdx.x;
    for (int e = tid; e < 384; e += blockDim.x) {
        int o = e / 3, c = e % 3;
        sw[e] = (o < 64) ? W[o * 6 + c] : (W[(o - 64) * 6 + 3 + c] - W[(o - 64) * 6 + c]);
    }
    __syncthreads();
    const float* p = &xT[((size_t)b * NP + n) * 3];
    float v0 = p[0], v1 = p[1], v2 = p[2];
    float* out = PQ + ((size_t)b * NP + n) * 128;
    for (int o = 0; o < 128; o++)
        out[o] = sw[o * 3] * v0 + sw[o * 3 + 1] * v1 + sw[o * 3 + 2] * v2;
}

__global__ void sumsqC_kernel(const float* __restrict__ xC, float* __restrict__ xx) {
    int b = blockIdx.y;
    int n = blockIdx.x * blockDim.x + threadIdx.x;
    float s = 0.f;
    for (int c = 0; c < 64; c++) {
        float v = xC[((size_t)b * 64 + c) * NP + n];
        s += v * v;
    }
    xx[b * NP + n] = s;
}

// ------------------------- kNN -------------------------
__global__ void knn3_kernel(const float* __restrict__ xT, const float* __restrict__ xx,
                            int* __restrict__ idx) {
    extern __shared__ float dist[];  // 8 * NP
    __shared__ float sctr[8][3];
    const int b = blockIdx.y, r0 = blockIdx.x * 8, tid = threadIdx.x;

    for (int e = tid; e < 24; e += 256)
        sctr[e / 3][e % 3] = xT[((size_t)b * NP + r0 + e / 3) * 3 + e % 3];
    __syncthreads();

    for (int j = tid; j < NP; j += 256) {
        const float* pj = xT + ((size_t)b * NP + j) * 3;
        float w0 = pj[0], w1 = pj[1], w2 = pj[2];
        float xxj = xx[b * NP + j];
#pragma unroll
        for (int r = 0; r < 8; r++) {
            float a = w0 * sctr[r][0] + w1 * sctr[r][1] + w2 * sctr[r][2];
            dist[r * NP + j] = 2.f * a - xxj;
        }
    }
    __syncthreads();

    const int w = tid >> 5, lane = tid & 31;
    float* dr = dist + w * NP;
    int* orow = idx + ((size_t)b * NP + r0 + w) * KNB;
    for (int k = 0; k < KNB; k++) {
        float bv = -FLT_MAX; int bi = -1;
        for (int j = lane; j < NP; j += 32) {
            float v = dr[j];
            if (v > bv) { bv = v; bi = j; }
        }
#pragma unroll
        for (int s = 16; s; s >>= 1) {
            float ov = __shfl_xor_sync(~0u, bv, s);
            int oi = __shfl_xor_sync(~0u, bi, s);
            if (ov > bv || (ov == bv && oi < bi)) { bv = ov; bi = oi; }
        }
        if (lane == 0) { orow[k] = bi; dr[bi] = -FLT_MAX; }
        __syncwarp();
    }
}

// C=64 kNN reading column-major features (coalesced)
__global__ void knnC_kernel(const float* __restrict__ xC, const float* __restrict__ xx,
                            int* __restrict__ idx) {
    extern __shared__ float dist[];  // 8 * NP
    __shared__ float sctr[8][64];
    const int b = blockIdx.y, r0 = blockIdx.x * 8, tid = threadIdx.x;

    for (int e = tid; e < 8 * 64; e += 256) {
        int r = e / 64, c = e % 64;
        sctr[r][c] = xC[((size_t)b * 64 + c) * NP + r0 + r];
    }
    __syncthreads();

    for (int j = tid; j < NP; j += 256) {
        float acc[8];
#pragma unroll
        for (int r = 0; r < 8; r++) acc[r] = 0.f;
        for (int c = 0; c < 64; c++) {
            float v = xC[((size_t)b * 64 + c) * NP + j];
#pragma unroll
            for (int r = 0; r < 8; r++) acc[r] += v * sctr[r][c];
        }
        float xxj = xx[b * NP + j];
#pragma unroll
        for (int r = 0; r < 8; r++) dist[r * NP + j] = 2.f * acc[r] - xxj;
    }
    __syncthreads();

    const int w = tid >> 5, lane = tid & 31;
    float* dr = dist + w * NP;
    int* orow = idx + ((size_t)b * NP + r0 + w) * KNB;
    for (int k = 0; k < KNB; k++) {
        float bv = -FLT_MAX; int bi = -1;
        for (int j = lane; j < NP; j += 32) {
            float v = dr[j];
            if (v > bv) { bv = v; bi = j; }
        }
#pragma unroll
        for (int s = 16; s; s >>= 1) {
            float ov = __shfl_xor_sync(~0u, bv, s);
            int oi = __shfl_xor_sync(~0u, bi, s);
            if (ov > bv || (ov == bv && oi < bi)) { bv = ov; bi = oi; }
        }
        if (lane == 0) { orow[k] = bi; dr[bi] = -FLT_MAX; }
        __syncwarp();
    }
}

// ------------------------- edge layer-2 (gather-add + GEMM + max) -----------
// h[k] = lrelu(P[idx[k]] + Q[n]); out = max_k lrelu(h @ W2)
template <int COUT>
__global__ __launch_bounds__(320) void edge2_kernel(
        const float* __restrict__ PQ, const int* __restrict__ idx,
        const float* __restrict__ W2T,  // [64][COUT]
        float* __restrict__ out, int old, int ooff, float* __restrict__ outC) {
    constexpr int NT = 320;
    extern __shared__ float sm[];
    float* sW2 = sm;                          // 64*COUT
    float* sH  = sW2 + 64 * COUT;             // 2*KNB*64  ([p][k][c])
    float* sO  = sH + 2 * KNB * 64;           // 2*KNB*COUT
    __shared__ float sQ[2][64];
    __shared__ int sidx[2][KNB];

    const int b = blockIdx.y, n0 = blockIdx.x * 2, tid = threadIdx.x;

    for (int e = tid; e < 64 * COUT; e += NT) sW2[e] = W2T[e];
    if (tid < 2 * KNB)
        sidx[tid / KNB][tid % KNB] = idx[((size_t)b * NP + n0 + tid / KNB) * KNB + tid % KNB];
    if (tid < 128)
        sQ[tid >> 6][tid & 63] = PQ[((size_t)b * NP + n0 + (tid >> 6)) * 128 + 64 + (tid & 63)];
    __syncthreads();

    for (int e = tid; e < 2 * KNB * 64; e += NT) {
        int p = e / (KNB * 64), r = e % (KNB * 64), k = r >> 6, c = r & 63;
        float v = PQ[((size_t)b * NP + sidx[p][k]) * 128 + c] + sQ[p][c];
        sH[e] = lrelu(v);
    }
    __syncthreads();

    constexpr int OT = COUT / 4;
    constexpr int TPP = (KNB / 4) * OT;  // tiles per point
    for (int t = tid; t < 2 * TPP; t += NT) {
        int p = t / TPP, r = t % TPP, kt = r / OT, ot = r % OT;
        const float* a0 = sH + ((size_t)p * KNB + kt * 4) * 64;
        const float* a1 = a0 + 64;
        const float* a2 = a1 + 64;
        const float* a3 = a2 + 64;
        float acc[4][4] = {};
#pragma unroll 4
        for (int c = 0; c < 64; c++) {
            float4 w = *(const float4*)(sW2 + c * COUT + ot * 4);
            float v0 = a0[c], v1 = a1[c], v2 = a2[c], v3 = a3[c];
            acc[0][0]+=v0*w.x; acc[0][1]+=v0*w.y; acc[0][2]+=v0*w.z; acc[0][3]+=v0*w.w;
            acc[1][0]+=v1*w.x; acc[1][1]+=v1*w.y; acc[1][2]+=v1*w.z; acc[1][3]+=v1*w.w;
            acc[2][0]+=v2*w.x; acc[2][1]+=v2*w.y; acc[2][2]+=v2*w.z; acc[2][3]+=v2*w.w;
            acc[3][0]+=v3*w.x; acc[3][1]+=v3*w.y; acc[3][2]+=v3*w.z; acc[3][3]+=v3*w.w;
        }
        float* d = sO + ((size_t)p * KNB + kt * 4) * COUT + ot * 4;
#pragma unroll
        for (int kj = 0; kj < 4; kj++)
#pragma unroll
            for (int oi = 0; oi < 4; oi++)
                d[kj * COUT + oi] = lrelu(acc[kj][oi]);
    }
    __syncthreads();

    for (int o = tid; o < 2 * COUT; o += NT) {
        int p = o / COUT, oo = o % COUT;
        const float* col = sO + (size_t)p * KNB * COUT + oo;
        float m = -FLT_MAX;
#pragma unroll 8
        for (int k = 0; k < KNB; k++) m = fmaxf(m, col[k * COUT]);
        int n = n0 + p;
        out[((size_t)b * NP + n) * old + ooff + oo] = m;
        if (outC) outC[((size_t)b * 64 + oo) * NP + n] = m;
    }
}

// E4: out[n,o] = lrelu(max_k P[idx[n,k],o] + Q[n,o])
__global__ void gathermax_kernel(const float* __restrict__ PQ, const int* __restrict__ idx,
                                 float* __restrict__ out, int old, int ooff) {
    __shared__ int sidx[2][KNB];
    int b = blockIdx.y, tid = threadIdx.x;
    int p = tid >> 6, oo = tid & 63;
    int n = blockIdx.x * 2 + p;
    if (tid < 2 * KNB)
        sidx[tid / KNB][tid % KNB] = idx[((size_t)b * NP + blockIdx.x * 2 + tid / KNB) * KNB + tid % KNB];
    __syncthreads();
    float m = -FLT_MAX;
#pragma unroll 4
    for (int k = 0; k < KNB; k++)
        m = fmaxf(m, PQ[((size_t)b * NP + sidx[p][k]) * 128 + oo]);
    float q = PQ[((size_t)b * NP + n) * 128 + 64 + oo];
    out[((size_t)b * NP + n) * old + ooff + oo] = lrelu(m + q);
}

// ------------------------- tiled pointwise conv (SGEMM) -------------------------
__global__ void pconv_kernel(const float* __restrict__ in, int ld, int coff,
                             const float* __restrict__ WT, int CIN, int OCP,
                             const float* __restrict__ bias, int bstride,
                             float* __restrict__ out, int outCM, int old, int ooff,
                             int OC, int act, float* __restrict__ pmax) {
    __shared__ float sA[16][68];
    __shared__ float sB[16][64];
    __shared__ float sR[16][64];
    const int b = blockIdx.z;
    const int n0 = blockIdx.x * 64, o0 = blockIdx.y * 64;
    const int tid = threadIdx.x;
    const int tx = tid % 16, ty = tid / 16;
    float acc[4][4] = {};

    for (int c0 = 0; c0 < CIN; c0 += 16) {
        {
            int p = tid >> 2, c4 = (tid & 3) * 4;
            const float* src = in + ((size_t)b * NP + n0 + p) * ld + coff + c0 + c4;
            float4 v = *(const float4*)src;
            sA[c4 + 0][p] = v.x; sA[c4 + 1][p] = v.y;
            sA[c4 + 2][p] = v.z; sA[c4 + 3][p] = v.w;
        }
        {
            int c = tid >> 4, o4 = (tid & 15) * 4;
            *(float4*)&sB[c][o4] = *(const float4*)(WT + (size_t)(c0 + c) * OCP + o0 + o4);
        }
        __syncthreads();
#pragma unroll
        for (int c = 0; c < 16; c++) {
            float4 av = *(const float4*)&sA[c][ty * 4];
            float4 bv = *(const float4*)&sB[c][tx * 4];
            acc[0][0]+=av.x*bv.x; acc[0][1]+=av.x*bv.y; acc[0][2]+=av.x*bv.z; acc[0][3]+=av.x*bv.w;
            acc[1][0]+=av.y*bv.x; acc[1][1]+=av.y*bv.y; acc[1][2]+=av.y*bv.z; acc[1][3]+=av.y*bv.w;
            acc[2][0]+=av.z*bv.x; acc[2][1]+=av.z*bv.y; acc[2][2]+=av.z*bv.z; acc[2][3]+=av.z*bv.w;
            acc[3][0]+=av.w*bv.x; acc[3][1]+=av.w*bv.y; acc[3][2]+=av.w*bv.z; acc[3][3]+=av.w*bv.w;
        }
        __syncthreads();
    }

    if (pmax) {
        // act assumed 1; reduce max over the 64 n's of this tile, emit per-block partial
#pragma unroll
        for (int j = 0; j < 4; j++) {
            float m = lrelu(acc[0][j]);
            m = fmaxf(m, lrelu(acc[1][j]));
            m = fmaxf(m, lrelu(acc[2][j]));
            m = fmaxf(m, lrelu(acc[3][j]));
            sR[ty][tx * 4 + j] = m;
        }
        __syncthreads();
        if (tid < 64) {
            float m = sR[0][tid];
#pragma unroll
            for (int r = 1; r < 16; r++) m = fmaxf(m, sR[r][tid]);
            pmax[((size_t)blockIdx.x * BN + b) * 1024 + o0 + tid] = m;
        }
        return;
    }

#pragma unroll
    for (int i = 0; i < 4; i++) {
        int n = n0 + ty * 4 + i;
#pragma unroll
        for (int j = 0; j < 4; j++) {
            int o = o0 + tx * 4 + j;
            if (o >= OC) continue;
            float v = acc[i][j];
            if (bias) v += bias[b * bstride + o];
            if (act) v = lrelu(v);
            if (outCM) out[((size_t)b * OC + o) * NP + n] = v;
            else out[((size_t)b * NP + n) * old + ooff + o] = v;
        }
    }
}

__global__ void pmaxreduce_kernel(const float* __restrict__ pm, float* __restrict__ out,
                                  int ostride, int ooff) {
    int gid = blockIdx.x * blockDim.x + threadIdx.x;
    if (gid >= BN * 1024) return;
    int b = gid / 1024, o = gid % 1024;
    float m = -FLT_MAX;
    for (int blk = 0; blk < 32; blk++)
        m = fmaxf(m, pm[((size_t)blk * BN + b) * 1024 + o]);
    out[(size_t)b * ostride + ooff + o] = m;
}

__global__ void fc_kernel(const float* __restrict__ in, int istride, int C,
                          const float* __restrict__ W, int wld, int O,
                          const float* __restrict__ bias, int bstride,
                          float* __restrict__ out, int ostride, int ooff, int act) {
    int b = blockIdx.x;
    int o = blockIdx.y * blockDim.x + threadIdx.x;
    if (o >= O) return;
    const float* ip = in + (size_t)b * istride;
    const float* wp = W + (size_t)o * wld;
    float s = 0.f;
    for (int c = 0; c < C; c++) s += ip[c] * wp[c];
    if (bias) s += bias[(size_t)b * bstride + o];
    if (act) s = lrelu(s);
    out[(size_t)b * ostride + ooff + o] = s;
}

// ------------------------- host -------------------------
extern "C" void kernel_launch(void* const* d_in, const int* in_sizes, int n_in,
                              void* d_out, int out_size) {
    const float* x    = (const float*)d_in[0];
    const float* l    = (const float*)d_in[1];
    const float* t_c1 = (const float*)d_in[2];
    const float* t_c2 = (const float*)d_in[3];
    const float* t_c3 = (const float*)d_in[4];
    const float* t_f1 = (const float*)d_in[5];
    const float* t_f2 = (const float*)d_in[6];
    const float* t_f3w= (const float*)d_in[7];
    const float* t_f3b= (const float*)d_in[8];
    const float* b1a  = (const float*)d_in[9];
    const float* b1b  = (const float*)d_in[10];
    const float* b2a  = (const float*)d_in[11];
    const float* b2b  = (const float*)d_in[12];
    const float* b3a  = (const float*)d_in[13];
    const float* m1   = (const float*)d_in[14];
    const float* m2   = (const float*)d_in[15];
    const float* h1   = (const float*)d_in[16];
    const float* h2   = (const float*)d_in[17];
    const float* h3   = (const float*)d_in[18];
    const float* h4   = (const float*)d_in[19];

    float *xTa, *xTb, *xx, *t128, *PQ, *xC, *pm, *cat, *vec, *t1024, *t512, *t256, *T9, *bsb, *hA, *hB, *WT;
    int* idxp;
    cudaGetSymbolAddress((void**)&xTa, g_xTa);
    cudaGetSymbolAddress((void**)&xTb, g_xTb);
    cudaGetSymbolAddress((void**)&xx, g_xx);
    cudaGetSymbolAddress((void**)&idxp, g_idx);
    cudaGetSymbolAddress((void**)&t128, g_t128);
    cudaGetSymbolAddress((void**)&PQ, g_PQ);
    cudaGetSymbolAddress((void**)&xC, g_xC);
    cudaGetSymbolAddress((void**)&pm, g_pm);
    cudaGetSymbolAddress((void**)&cat, g_cat);
    cudaGetSymbolAddress((void**)&vec, g_vec);
    cudaGetSymbolAddress((void**)&t1024, g_t1024);
    cudaGetSymbolAddress((void**)&t512, g_t512);
    cudaGetSymbolAddress((void**)&t256, g_t256);
    cudaGetSymbolAddress((void**)&T9, g_T9);
    cudaGetSymbolAddress((void**)&bsb, g_bias);
    cudaGetSymbolAddress((void**)&hA, g_hA);
    cudaGetSymbolAddress((void**)&hB, g_hB);
    cudaGetSymbolAddress((void**)&WT, g_WT);

    const int KNN_SMEM = 8 * NP * 4;                                    // 65536
    const int E128 = (64*128 + 2*KNB*64 + 2*KNB*128) * 4;               // 94208
    const int E64  = (64*64  + 2*KNB*64 + 2*KNB*64) * 4;                // 57344
    cudaFuncSetAttribute(knn3_kernel, cudaFuncAttributeMaxDynamicSharedMemorySize, KNN_SMEM);
    cudaFuncSetAttribute(knnC_kernel, cudaFuncAttributeMaxDynamicSharedMemorySize, KNN_SMEM);
    cudaFuncSetAttribute(edge2_kernel<128>, cudaFuncAttributeMaxDynamicSharedMemorySize, E128);
    cudaFuncSetAttribute(edge2_kernel<64>,  cudaFuncAttributeMaxDynamicSharedMemorySize, E64);

    // ---- weight prep ----
    {
        struct TW { const float* W; int O, C, ldW, coff; int off, OCP; };
        TW tws[] = {
            {t_c2, 128, 64, 64, 0, OFF_tc2, 128},
            {t_c3, 1024, 128, 128, 0, OFF_tc3, 1024},
            {b1b, 64, 64, 64, 0, OFF_b1b, 64},
            {b2b, 64, 64, 64, 0, OFF_b2b, 64},
            {m1, 1024, 192, 192, 0, OFF_m1, 1024},
            {h1, 256, 192, 1280, 1088, OFF_h1p, 256},
            {h2, 256, 256, 256, 0, OFF_h2, 256},
            {h3, 128, 256, 256, 0, OFF_h3, 128},
            {h4, 50, 128, 128, 0, OFF_h4, 64},
        };
        for (auto& t : tws) {
            int n = t.C * t.OCP;
            tw_kernel<<<(n + 255) / 256, 256>>>(t.W, t.O, t.C, t.ldW, t.coff, WT + t.off, t.OCP);
        }
        tw2_kernel<<<(64 * 128 + 255) / 256, 256>>>(b2a, 64, WT + OFF_pq2);
        tw2_kernel<<<(64 * 128 + 255) / 256, 256>>>(b3a, 64, WT + OFF_pq3);
    }

    // ---- transform net ----
    prep_kernel<<<dim3(NP / 256, BN), 256>>>(x, xTa, xx);
    knn3_kernel<<<dim3(NP / 8, BN), 256, KNN_SMEM>>>(xTa, xx, idxp);
    pq3_kernel<<<dim3(NP / 256, BN), 256>>>(xTa, t_c1, PQ);
    edge2_kernel<128><<<dim3(NP / 2, BN), 320, E128>>>(PQ, idxp, WT + OFF_tc2, t128, 128, 0, nullptr);
    pconv_kernel<<<dim3(32, 16, BN), 256>>>(t128, 128, 0, WT + OFF_tc3, 128, 1024,
                                            nullptr, 0, nullptr, 0, 0, 0, 1024, 1, pm);
    pmaxreduce_kernel<<<(BN * 1024 + 255) / 256, 256>>>(pm, t1024, 1024, 0);
    fc_kernel<<<dim3(BN, 2), 256>>>(t1024, 1024, 1024, t_f1, 1024, 512, nullptr, 0, t512, 512, 0, 1);
    fc_kernel<<<dim3(BN, 1), 256>>>(t512, 512, 512, t_f2, 512, 256, nullptr, 0, t256, 256, 0, 1);
    fc_kernel<<<dim3(BN, 1), 256>>>(t256, 256, 256, t_f3w, 256, 9, t_f3b, 0, T9, 9, 0, 0);
    transform_kernel<<<dim3(NP / 256, BN), 256>>>(x, T9, xTb, xx);

    // ---- edge block 1 ----
    knn3_kernel<<<dim3(NP / 8, BN), 256, KNN_SMEM>>>(xTb, xx, idxp);
    pq3_kernel<<<dim3(NP / 256, BN), 256>>>(xTb, b1a, PQ);
    edge2_kernel<64><<<dim3(NP / 2, BN), 320, E64>>>(PQ, idxp, WT + OFF_b1b, cat, 192, 0, xC);

    // ---- edge block 2 ----
    sumsqC_kernel<<<dim3(NP / 256, BN), 256>>>(xC, xx);
    knnC_kernel<<<dim3(NP / 8, BN), 256, KNN_SMEM>>>(xC, xx, idxp);
    pconv_kernel<<<dim3(32, 2, BN), 256>>>(cat, 192, 0, WT + OFF_pq2, 64, 128,
                                           nullptr, 0, PQ, 0, 128, 0, 128, 0, nullptr);
    edge2_kernel<64><<<dim3(NP / 2, BN), 320, E64>>>(PQ, idxp, WT + OFF_b2b, cat, 192, 64, xC);

    // ---- edge block 3 (collapsed) ----
    sumsqC_kernel<<<dim3(NP / 256, BN), 256>>>(xC, xx);
    knnC_kernel<<<dim3(NP / 8, BN), 256, KNN_SMEM>>>(xC, xx, idxp);
    pconv_kernel<<<dim3(32, 2, BN), 256>>>(cat, 192, 64, WT + OFF_pq3, 64, 128,
                                           nullptr, 0, PQ, 0, 128, 0, 128, 0, nullptr);
    gathermax_kernel<<<dim3(NP / 2, BN), 128>>>(PQ, idxp, cat, 192, 128);

    // ---- global features ----
    pconv_kernel<<<dim3(32, 16, BN), 256>>>(cat, 192, 0, WT + OFF_m1, 192, 1024,
                                            nullptr, 0, nullptr, 0, 0, 0, 1024, 1, pm);
    pmaxreduce_kernel<<<(BN * 1024 + 255) / 256, 256>>>(pm, vec, 1088, 0);
    fc_kernel<<<dim3(BN, 1), 256>>>(l, 16, 16, m2, 16, 64, nullptr, 0, vec, 1088, 1024, 1);
    fc_kernel<<<dim3(BN, 1), 256>>>(vec, 1088, 1088, h1, 1280, 256, nullptr, 0, bsb, 256, 0, 0);

    // ---- head ----
    pconv_kernel<<<dim3(32, 4, BN), 256>>>(cat, 192, 0, WT + OFF_h1p, 192, 256,
                                           bsb, 256, hA, 0, 256, 0, 256, 1, nullptr);
    pconv_kernel<<<dim3(32, 4, BN), 256>>>(hA, 256, 0, WT + OFF_h2, 256, 256,
                                           nullptr, 0, hB, 0, 256, 0, 256, 1, nullptr);
    pconv_kernel<<<dim3(32, 2, BN), 256>>>(hB, 256, 0, WT + OFF_h3, 256, 128,
                                           nullptr, 0, hA, 0, 128, 0, 128, 1, nullptr);
    pconv_kernel<<<dim3(32, 1, BN), 256>>>(hA, 128, 0, WT + OFF_h4, 128, 64,
                                           nullptr, 0, (float*)d_out, 1, 0, 0, 50, 0, nullptr);
}

// round 6
// speedup vs baseline: 2.0759x; 1.0640x over previous
#include <cuda_runtime.h>
#include <float.h>

#define BN 8
#define NP 2048
#define KNB 40

__device__ __forceinline__ float lrelu(float v) { return v > 0.f ? v : 0.2f * v; }

// ------------------------- scratch (device globals) -------------------------
__device__ __align__(16) float g_xTa[BN * NP * 3];
__device__ __align__(16) float g_xTb[BN * NP * 3];
__device__ __align__(16) float g_xx[BN * NP];
__device__ __align__(16) int   g_idx[BN * NP * KNB];
__device__ __align__(16) float g_t128[BN * NP * 128];
__device__ __align__(16) float g_PQ[BN * NP * 128];
__device__ __align__(16) float g_xC[BN * 64 * NP];
__device__ __align__(16) float g_pm[32 * BN * 1024];
__device__ __align__(16) float g_cat[BN * NP * 192];
__device__ __align__(16) float g_vec[BN * 1088];
__device__ __align__(16) float g_t1024[BN * 1024];
__device__ __align__(16) float g_t512[BN * 512];
__device__ __align__(16) float g_t256[BN * 256];
__device__ __align__(16) float g_T9[BN * 9];
__device__ __align__(16) float g_bias[BN * 256];
__device__ __align__(16) float g_hA[BN * NP * 256];
__device__ __align__(16) float g_hB[BN * NP * 256];

// transposed-weight pool
#define OFF_tc2 0
#define OFF_tc3 (OFF_tc2 + 64*128)
#define OFF_b1b (OFF_tc3 + 128*1024)
#define OFF_b2b (OFF_b1b + 64*64)
#define OFF_m1  (OFF_b2b + 64*64)
#define OFF_h1p (OFF_m1  + 192*1024)
#define OFF_h2  (OFF_h1p + 192*256)
#define OFF_h3  (OFF_h2  + 256*256)
#define OFF_h4  (OFF_h3  + 256*128)
#define OFF_pq2 (OFF_h4  + 128*64)
#define OFF_pq3 (OFF_pq2 + 64*128)
#define WT_TOTAL (OFF_pq3 + 64*128)
__device__ __align__(16) float g_WT[WT_TOTAL];

// ------------------------- prep / small kernels -------------------------
__global__ void tw_kernel(const float* __restrict__ W, int O, int C, int ldW,
                          int coff, float* __restrict__ WT, int OCP) {
    int e = blockIdx.x * blockDim.x + threadIdx.x;
    if (e >= C * OCP) return;
    int c = e / OCP, o = e % OCP;
    WT[e] = (o < O) ? W[(size_t)o * ldW + coff + c] : 0.f;
}

// PQ weight: cols [0,64) = Wa^T, [64,128) = (Wb - Wa)^T.  W: (64, 2*CIN) row-major
__global__ void tw2_kernel(const float* __restrict__ W, int CIN, float* __restrict__ WT) {
    int e = blockIdx.x * blockDim.x + threadIdx.x;
    if (e >= CIN * 128) return;
    int c = e / 128, o = e % 128;
    if (o < 64) WT[e] = W[(size_t)o * 2 * CIN + c];
    else {
        int oo = o - 64;
        WT[e] = W[(size_t)oo * 2 * CIN + CIN + c] - W[(size_t)oo * 2 * CIN + c];
    }
}

__global__ void prep_kernel(const float* __restrict__ x, float* __restrict__ xT,
                            float* __restrict__ xx) {
    int b = blockIdx.y;
    int n = blockIdx.x * blockDim.x + threadIdx.x;
    float v0 = x[((size_t)b * 3 + 0) * NP + n];
    float v1 = x[((size_t)b * 3 + 1) * NP + n];
    float v2 = x[((size_t)b * 3 + 2) * NP + n];
    float* o = &xT[((size_t)b * NP + n) * 3];
    o[0] = v0; o[1] = v1; o[2] = v2;
    xx[b * NP + n] = v0 * v0 + v1 * v1 + v2 * v2;
}

__global__ void transform_kernel(const float* __restrict__ x, const float* __restrict__ T9,
                                 float* __restrict__ xT, float* __restrict__ xx) {
    int b = blockIdx.y;
    int n = blockIdx.x * blockDim.x + threadIdx.x;
    const float* T = &T9[b * 9];
    float v0 = x[((size_t)b * 3 + 0) * NP + n];
    float v1 = x[((size_t)b * 3 + 1) * NP + n];
    float v2 = x[((size_t)b * 3 + 2) * NP + n];
    float y0 = v0 * T[0] + v1 * T[3] + v2 * T[6];
    float y1 = v0 * T[1] + v1 * T[4] + v2 * T[7];
    float y2 = v0 * T[2] + v1 * T[5] + v2 * T[8];
    float* o = &xT[((size_t)b * NP + n) * 3];
    o[0] = y0; o[1] = y1; o[2] = y2;
    xx[b * NP + n] = y0 * y0 + y1 * y1 + y2 * y2;
}

// P|Q for CIN=3 layers: out[n] = [Wa@x_n (64) | (Wb-Wa)@x_n (64)]
__global__ void pq3_kernel(const float* __restrict__ xT, const float* __restrict__ W,
                           float* __restrict__ PQ) {
    __shared__ float sw[128 * 3];
    int b = blockIdx.y;
    int n = blockIdx.x * blockDim.x + threadIdx.x;
    int tid = threadIdx.x;
    for (int e = tid; e < 384; e += blockDim.x) {
        int o = e / 3, c = e % 3;
        sw[e] = (o < 64) ? W[o * 6 + c] : (W[(o - 64) * 6 + 3 + c] - W[(o - 64) * 6 + c]);
    }
    __syncthreads();
    const float* p = &xT[((size_t)b * NP + n) * 3];
    float v0 = p[0], v1 = p[1], v2 = p[2];
    float* out = PQ + ((size_t)b * NP + n) * 128;
    for (int o = 0; o < 128; o++)
        out[o] = sw[o * 3] * v0 + sw[o * 3 + 1] * v1 + sw[o * 3 + 2] * v2;
}

__global__ void sumsqC_kernel(const float* __restrict__ xC, float* __restrict__ xx) {
    int b = blockIdx.y;
    int n = blockIdx.x * blockDim.x + threadIdx.x;
    float s = 0.f;
    for (int c = 0; c < 64; c++) {
        float v = xC[((size_t)b * 64 + c) * NP + n];
        s += v * v;
    }
    xx[b * NP + n] = s;
}

// ------------------------- kNN selection (lazy per-lane argmax) -------------
// Each lane owns the stride-32 slice {lane + 32*t}. Per extraction only the
// winning lane rescans its 64 elements; everyone else reuses its cached max.
__device__ __forceinline__ void knn_select(float* dr, int* orow, int lane) {
    float lv = -FLT_MAX; int li = -1;
#pragma unroll 8
    for (int t = 0; t < NP / 32; t++) {
        int j = lane + (t << 5);
        float v = dr[j];
        if (v > lv) { lv = v; li = j; }
    }
    for (int k = 0; k < KNB; k++) {
        float bv = lv; int bi = li;
#pragma unroll
        for (int s = 16; s; s >>= 1) {
            float ov = __shfl_xor_sync(~0u, bv, s);
            int oi = __shfl_xor_sync(~0u, bi, s);
            if (ov > bv || (ov == bv && oi < bi)) { bv = ov; bi = oi; }
        }
        if (lane == 0) orow[k] = bi;
        if ((bi & 31) == lane) {
            dr[bi] = -FLT_MAX;
            lv = -FLT_MAX; li = -1;
#pragma unroll 8
            for (int t = 0; t < NP / 32; t++) {
                int j = lane + (t << 5);
                float v = dr[j];
                if (v > lv) { lv = v; li = j; }
            }
        }
    }
}

__global__ void knn3_kernel(const float* __restrict__ xT, const float* __restrict__ xx,
                            int* __restrict__ idx) {
    extern __shared__ float dist[];  // 8 * NP
    __shared__ float sctr[8][3];
    const int b = blockIdx.y, r0 = blockIdx.x * 8, tid = threadIdx.x;

    for (int e = tid; e < 24; e += 256)
        sctr[e / 3][e % 3] = xT[((size_t)b * NP + r0 + e / 3) * 3 + e % 3];
    __syncthreads();

    for (int j = tid; j < NP; j += 256) {
        const float* pj = xT + ((size_t)b * NP + j) * 3;
        float w0 = pj[0], w1 = pj[1], w2 = pj[2];
        float xxj = xx[b * NP + j];
#pragma unroll
        for (int r = 0; r < 8; r++) {
            float a = w0 * sctr[r][0] + w1 * sctr[r][1] + w2 * sctr[r][2];
            dist[r * NP + j] = 2.f * a - xxj;
        }
    }
    __syncthreads();

    const int w = tid >> 5, lane = tid & 31;
    knn_select(dist + w * NP, idx + ((size_t)b * NP + r0 + w) * KNB, lane);
}

// C=64 kNN reading column-major features (coalesced)
__global__ void knnC_kernel(const float* __restrict__ xC, const float* __restrict__ xx,
                            int* __restrict__ idx) {
    extern __shared__ float dist[];  // 8 * NP
    __shared__ float sctr[8][64];
    const int b = blockIdx.y, r0 = blockIdx.x * 8, tid = threadIdx.x;

    for (int e = tid; e < 8 * 64; e += 256) {
        int r = e / 64, c = e % 64;
        sctr[r][c] = xC[((size_t)b * 64 + c) * NP + r0 + r];
    }
    __syncthreads();

    for (int j = tid; j < NP; j += 256) {
        float acc[8];
#pragma unroll
        for (int r = 0; r < 8; r++) acc[r] = 0.f;
        for (int c = 0; c < 64; c++) {
            float v = xC[((size_t)b * 64 + c) * NP + j];
#pragma unroll
            for (int r = 0; r < 8; r++) acc[r] += v * sctr[r][c];
        }
        float xxj = xx[b * NP + j];
#pragma unroll
        for (int r = 0; r < 8; r++) dist[r * NP + j] = 2.f * acc[r] - xxj;
    }
    __syncthreads();

    const int w = tid >> 5, lane = tid & 31;
    knn_select(dist + w * NP, idx + ((size_t)b * NP + r0 + w) * KNB, lane);
}

// ------------------------- edge layer-2 (gather-add + GEMM + fused max) -----
// h[k] = lrelu(P[idx[k]] + Q[n]); out = max_k lrelu(h @ W2)
template <int COUT>
__global__ __launch_bounds__(320) void edge2_kernel(
        const float* __restrict__ PQ, const int* __restrict__ idx,
        const float* __restrict__ W2T,  // [64][COUT]
        float* __restrict__ out, int old, int ooff, float* __restrict__ outC) {
    constexpr int NT = 320;
    constexpr int KT = KNB / 4;  // 10 k-groups
    extern __shared__ float sm[];
    float* sW2 = sm;                          // 64*COUT
    float* sH  = sW2 + 64 * COUT;             // 2*KNB*64  ([p][k][c])
    float* sP  = sH + 2 * KNB * 64;           // 2*KT*COUT partial maxes
    __shared__ float sQ[2][64];
    __shared__ int sidx[2][KNB];

    const int b = blockIdx.y, n0 = blockIdx.x * 2, tid = threadIdx.x;

    for (int e = tid; e < 64 * COUT; e += NT) sW2[e] = W2T[e];
    if (tid < 2 * KNB)
        sidx[tid / KNB][tid % KNB] = idx[((size_t)b * NP + n0 + tid / KNB) * KNB + tid % KNB];
    if (tid < 128)
        sQ[tid >> 6][tid & 63] = PQ[((size_t)b * NP + n0 + (tid >> 6)) * 128 + 64 + (tid & 63)];
    __syncthreads();

    for (int e = tid; e < 2 * KNB * 64; e += NT) {
        int p = e / (KNB * 64), r = e % (KNB * 64), k = r >> 6, c = r & 63;
        float v = PQ[((size_t)b * NP + sidx[p][k]) * 128 + c] + sQ[p][c];
        sH[e] = lrelu(v);
    }
    __syncthreads();

    constexpr int OT = COUT / 4;
    constexpr int TPP = KT * OT;  // tiles per point
    for (int t = tid; t < 2 * TPP; t += NT) {
        int p = t / TPP, r = t % TPP, kt = r / OT, ot = r % OT;
        const float* a0 = sH + ((size_t)p * KNB + kt * 4) * 64;
        const float* a1 = a0 + 64;
        const float* a2 = a1 + 64;
        const float* a3 = a2 + 64;
        float acc[4][4] = {};
#pragma unroll 4
        for (int c = 0; c < 64; c++) {
            float4 w = *(const float4*)(sW2 + c * COUT + ot * 4);
            float v0 = a0[c], v1 = a1[c], v2 = a2[c], v3 = a3[c];
            acc[0][0]+=v0*w.x; acc[0][1]+=v0*w.y; acc[0][2]+=v0*w.z; acc[0][3]+=v0*w.w;
            acc[1][0]+=v1*w.x; acc[1][1]+=v1*w.y; acc[1][2]+=v1*w.z; acc[1][3]+=v1*w.w;
            acc[2][0]+=v2*w.x; acc[2][1]+=v2*w.y; acc[2][2]+=v2*w.z; acc[2][3]+=v2*w.w;
            acc[3][0]+=v3*w.x; acc[3][1]+=v3*w.y; acc[3][2]+=v3*w.z; acc[3][3]+=v3*w.w;
        }
        // fused max over the 4 k-rows of this tile
        float* d = sP + ((size_t)p * KT + kt) * COUT + ot * 4;
#pragma unroll
        for (int oi = 0; oi < 4; oi++) {
            float m = lrelu(acc[0][oi]);
            m = fmaxf(m, lrelu(acc[1][oi]));
            m = fmaxf(m, lrelu(acc[2][oi]));
            m = fmaxf(m, lrelu(acc[3][oi]));
            d[oi] = m;
        }
    }
    __syncthreads();

    for (int o = tid; o < 2 * COUT; o += NT) {
        int p = o / COUT, oo = o % COUT;
        const float* col = sP + (size_t)p * KT * COUT + oo;
        float m = col[0];
#pragma unroll
        for (int kt = 1; kt < KT; kt++) m = fmaxf(m, col[kt * COUT]);
        int n = n0 + p;
        out[((size_t)b * NP + n) * old + ooff + oo] = m;
        if (outC) outC[((size_t)b * 64 + oo) * NP + n] = m;
    }
}

// E4: out[n,o] = lrelu(max_k P[idx[n,k],o] + Q[n,o])
__global__ void gathermax_kernel(const float* __restrict__ PQ, const int* __restrict__ idx,
                                 float* __restrict__ out, int old, int ooff) {
    __shared__ int sidx[2][KNB];
    int b = blockIdx.y, tid = threadIdx.x;
    int p = tid >> 6, oo = tid & 63;
    int n = blockIdx.x * 2 + p;
    if (tid < 2 * KNB)
        sidx[tid / KNB][tid % KNB] = idx[((size_t)b * NP + blockIdx.x * 2 + tid / KNB) * KNB + tid % KNB];
    __syncthreads();
    float m = -FLT_MAX;
#pragma unroll 4
    for (int k = 0; k < KNB; k++)
        m = fmaxf(m, PQ[((size_t)b * NP + sidx[p][k]) * 128 + oo]);
    float q = PQ[((size_t)b * NP + n) * 128 + 64 + oo];
    out[((size_t)b * NP + n) * old + ooff + oo] = lrelu(m + q);
}

// ------------------------- tiled pointwise conv (SGEMM) -------------------------
__global__ void pconv_kernel(const float* __restrict__ in, int ld, int coff,
                             const float* __restrict__ WT, int CIN, int OCP,
                             const float* __restrict__ bias, int bstride,
                             float* __restrict__ out, int outCM, int old, int ooff,
                             int OC, int act, float* __restrict__ pmax) {
    __shared__ float sA[16][68];
    __shared__ float sB[16][64];
    __shared__ float sR[16][64];
    const int b = blockIdx.z;
    const int n0 = blockIdx.x * 64, o0 = blockIdx.y * 64;
    const int tid = threadIdx.x;
    const int tx = tid % 16, ty = tid / 16;
    float acc[4][4] = {};

    for (int c0 = 0; c0 < CIN; c0 += 16) {
        {
            int p = tid >> 2, c4 = (tid & 3) * 4;
            const float* src = in + ((size_t)b * NP + n0 + p) * ld + coff + c0 + c4;
            float4 v = *(const float4*)src;
            sA[c4 + 0][p] = v.x; sA[c4 + 1][p] = v.y;
            sA[c4 + 2][p] = v.z; sA[c4 + 3][p] = v.w;
        }
        {
            int c = tid >> 4, o4 = (tid & 15) * 4;
            *(float4*)&sB[c][o4] = *(const float4*)(WT + (size_t)(c0 + c) * OCP + o0 + o4);
        }
        __syncthreads();
#pragma unroll
        for (int c = 0; c < 16; c++) {
            float4 av = *(const float4*)&sA[c][ty * 4];
            float4 bv = *(const float4*)&sB[c][tx * 4];
            acc[0][0]+=av.x*bv.x; acc[0][1]+=av.x*bv.y; acc[0][2]+=av.x*bv.z; acc[0][3]+=av.x*bv.w;
            acc[1][0]+=av.y*bv.x; acc[1][1]+=av.y*bv.y; acc[1][2]+=av.y*bv.z; acc[1][3]+=av.y*bv.w;
            acc[2][0]+=av.z*bv.x; acc[2][1]+=av.z*bv.y; acc[2][2]+=av.z*bv.z; acc[2][3]+=av.z*bv.w;
            acc[3][0]+=av.w*bv.x; acc[3][1]+=av.w*bv.y; acc[3][2]+=av.w*bv.z; acc[3][3]+=av.w*bv.w;
        }
        __syncthreads();
    }

    if (pmax) {
#pragma unroll
        for (int j = 0; j < 4; j++) {
            float m = lrelu(acc[0][j]);
            m = fmaxf(m, lrelu(acc[1][j]));
            m = fmaxf(m, lrelu(acc[2][j]));
            m = fmaxf(m, lrelu(acc[3][j]));
            sR[ty][tx * 4 + j] = m;
        }
        __syncthreads();
        if (tid < 64) {
            float m = sR[0][tid];
#pragma unroll
            for (int r = 1; r < 16; r++) m = fmaxf(m, sR[r][tid]);
            pmax[((size_t)blockIdx.x * BN + b) * 1024 + o0 + tid] = m;
        }
        return;
    }

#pragma unroll
    for (int i = 0; i < 4; i++) {
        int n = n0 + ty * 4 + i;
#pragma unroll
        for (int j = 0; j < 4; j++) {
            int o = o0 + tx * 4 + j;
            if (o >= OC) continue;
            float v = acc[i][j];
            if (bias) v += bias[b * bstride + o];
            if (act) v = lrelu(v);
            if (outCM) out[((size_t)b * OC + o) * NP + n] = v;
            else out[((size_t)b * NP + n) * old + ooff + o] = v;
        }
    }
}

__global__ void pmaxreduce_kernel(const float* __restrict__ pm, float* __restrict__ out,
                                  int ostride, int ooff) {
    int gid = blockIdx.x * blockDim.x + threadIdx.x;
    if (gid >= BN * 1024) return;
    int b = gid / 1024, o = gid % 1024;
    float m = -FLT_MAX;
    for (int blk = 0; blk < 32; blk++)
        m = fmaxf(m, pm[((size_t)blk * BN + b) * 1024 + o]);
    out[(size_t)b * ostride + ooff + o] = m;
}

__global__ void fc_kernel(const float* __restrict__ in, int istride, int C,
                          const float* __restrict__ W, int wld, int O,
                          const float* __restrict__ bias, int bstride,
                          float* __restrict__ out, int ostride, int ooff, int act) {
    int b = blockIdx.x;
    int o = blockIdx.y * blockDim.x + threadIdx.x;
    if (o >= O) return;
    const float* ip = in + (size_t)b * istride;
    const float* wp = W + (size_t)o * wld;
    float s = 0.f;
    for (int c = 0; c < C; c++) s += ip[c] * wp[c];
    if (bias) s += bias[(size_t)b * bstride + o];
    if (act) s = lrelu(s);
    out[(size_t)b * ostride + ooff + o] = s;
}

// ------------------------- host -------------------------
extern "C" void kernel_launch(void* const* d_in, const int* in_sizes, int n_in,
                              void* d_out, int out_size) {
    const float* x    = (const float*)d_in[0];
    const float* l    = (const float*)d_in[1];
    const float* t_c1 = (const float*)d_in[2];
    const float* t_c2 = (const float*)d_in[3];
    const float* t_c3 = (const float*)d_in[4];
    const float* t_f1 = (const float*)d_in[5];
    const float* t_f2 = (const float*)d_in[6];
    const float* t_f3w= (const float*)d_in[7];
    const float* t_f3b= (const float*)d_in[8];
    const float* b1a  = (const float*)d_in[9];
    const float* b1b  = (const float*)d_in[10];
    const float* b2a  = (const float*)d_in[11];
    const float* b2b  = (const float*)d_in[12];
    const float* b3a  = (const float*)d_in[13];
    const float* m1   = (const float*)d_in[14];
    const float* m2   = (const float*)d_in[15];
    const float* h1   = (const float*)d_in[16];
    const float* h2   = (const float*)d_in[17];
    const float* h3   = (const float*)d_in[18];
    const float* h4   = (const float*)d_in[19];

    float *xTa, *xTb, *xx, *t128, *PQ, *xC, *pm, *cat, *vec, *t1024, *t512, *t256, *T9, *bsb, *hA, *hB, *WT;
    int* idxp;
    cudaGetSymbolAddress((void**)&xTa, g_xTa);
    cudaGetSymbolAddress((void**)&xTb, g_xTb);
    cudaGetSymbolAddress((void**)&xx, g_xx);
    cudaGetSymbolAddress((void**)&idxp, g_idx);
    cudaGetSymbolAddress((void**)&t128, g_t128);
    cudaGetSymbolAddress((void**)&PQ, g_PQ);
    cudaGetSymbolAddress((void**)&xC, g_xC);
    cudaGetSymbolAddress((void**)&pm, g_pm);
    cudaGetSymbolAddress((void**)&cat, g_cat);
    cudaGetSymbolAddress((void**)&vec, g_vec);
    cudaGetSymbolAddress((void**)&t1024, g_t1024);
    cudaGetSymbolAddress((void**)&t512, g_t512);
    cudaGetSymbolAddress((void**)&t256, g_t256);
    cudaGetSymbolAddress((void**)&T9, g_T9);
    cudaGetSymbolAddress((void**)&bsb, g_bias);
    cudaGetSymbolAddress((void**)&hA, g_hA);
    cudaGetSymbolAddress((void**)&hB, g_hB);
    cudaGetSymbolAddress((void**)&WT, g_WT);

    const int KNN_SMEM = 8 * NP * 4;                                    // 65536
    const int E128 = (64*128 + 2*KNB*64 + 2*(KNB/4)*128) * 4;           // 63488
    const int E64  = (64*64  + 2*KNB*64 + 2*(KNB/4)*64) * 4;            // 41984
    cudaFuncSetAttribute(knn3_kernel, cudaFuncAttributeMaxDynamicSharedMemorySize, KNN_SMEM);
    cudaFuncSetAttribute(knnC_kernel, cudaFuncAttributeMaxDynamicSharedMemorySize, KNN_SMEM);
    cudaFuncSetAttribute(edge2_kernel<128>, cudaFuncAttributeMaxDynamicSharedMemorySize, E128);
    cudaFuncSetAttribute(edge2_kernel<64>,  cudaFuncAttributeMaxDynamicSharedMemorySize, E64);

    // ---- front of pipeline ordered so ncu (-s 5 -c 1) profiles edge2<128> ----
    tw_kernel<<<(64*128 + 255) / 256, 256>>>(t_c2, 128, 64, 64, 0, WT + OFF_tc2, 128);       // 0
    tw_kernel<<<(128*1024 + 255) / 256, 256>>>(t_c3, 1024, 128, 128, 0, WT + OFF_tc3, 1024); // 1
    prep_kernel<<<dim3(NP / 256, BN), 256>>>(x, xTa, xx);                                    // 2
    knn3_kernel<<<dim3(NP / 8, BN), 256, KNN_SMEM>>>(xTa, xx, idxp);                         // 3
    pq3_kernel<<<dim3(NP / 256, BN), 256>>>(xTa, t_c1, PQ);                                  // 4
    edge2_kernel<128><<<dim3(NP / 2, BN), 320, E128>>>(PQ, idxp, WT + OFF_tc2, t128, 128, 0, nullptr); // 5 (profiled)

    // ---- remaining weight prep ----
    {
        struct TW { const float* W; int O, C, ldW, coff; int off, OCP; };
        TW tws[] = {
            {b1b, 64, 64, 64, 0, OFF_b1b, 64},
            {b2b, 64, 64, 64, 0, OFF_b2b, 64},
            {m1, 1024, 192, 192, 0, OFF_m1, 1024},
            {h1, 256, 192, 1280, 1088, OFF_h1p, 256},
            {h2, 256, 256, 256, 0, OFF_h2, 256},
            {h3, 128, 256, 256, 0, OFF_h3, 128},
            {h4, 50, 128, 128, 0, OFF_h4, 64},
        };
        for (auto& t : tws) {
            int n = t.C * t.OCP;
            tw_kernel<<<(n + 255) / 256, 256>>>(t.W, t.O, t.C, t.ldW, t.coff, WT + t.off, t.OCP);
        }
        tw2_kernel<<<(64 * 128 + 255) / 256, 256>>>(b2a, 64, WT + OFF_pq2);
        tw2_kernel<<<(64 * 128 + 255) / 256, 256>>>(b3a, 64, WT + OFF_pq3);
    }

    // ---- transform net (cont.) ----
    pconv_kernel<<<dim3(32, 16, BN), 256>>>(t128, 128, 0, WT + OFF_tc3, 128, 1024,
                                            nullptr, 0, nullptr, 0, 0, 0, 1024, 1, pm);
    pmaxreduce_kernel<<<(BN * 1024 + 255) / 256, 256>>>(pm, t1024, 1024, 0);
    fc_kernel<<<dim3(BN, 2), 256>>>(t1024, 1024, 1024, t_f1, 1024, 512, nullptr, 0, t512, 512, 0, 1);
    fc_kernel<<<dim3(BN, 1), 256>>>(t512, 512, 512, t_f2, 512, 256, nullptr, 0, t256, 256, 0, 1);
    fc_kernel<<<dim3(BN, 1), 256>>>(t256, 256, 256, t_f3w, 256, 9, t_f3b, 0, T9, 9, 0, 0);
    transform_kernel<<<dim3(NP / 256, BN), 256>>>(x, T9, xTb, xx);

    // ---- edge block 1 ----
    knn3_kernel<<<dim3(NP / 8, BN), 256, KNN_SMEM>>>(xTb, xx, idxp);
    pq3_kernel<<<dim3(NP / 256, BN), 256>>>(xTb, b1a, PQ);
    edge2_kernel<64><<<dim3(NP / 2, BN), 320, E64>>>(PQ, idxp, WT + OFF_b1b, cat, 192, 0, xC);

    // ---- edge block 2 ----
    sumsqC_kernel<<<dim3(NP / 256, BN), 256>>>(xC, xx);
    knnC_kernel<<<dim3(NP / 8, BN), 256, KNN_SMEM>>>(xC, xx, idxp);
    pconv_kernel<<<dim3(32, 2, BN), 256>>>(cat, 192, 0, WT + OFF_pq2, 64, 128,
                                           nullptr, 0, PQ, 0, 128, 0, 128, 0, nullptr);
    edge2_kernel<64><<<dim3(NP / 2, BN), 320, E64>>>(PQ, idxp, WT + OFF_b2b, cat, 192, 64, xC);

    // ---- edge block 3 (collapsed) ----
    sumsqC_kernel<<<dim3(NP / 256, BN), 256>>>(xC, xx);
    knnC_kernel<<<dim3(NP / 8, BN), 256, KNN_SMEM>>>(xC, xx, idxp);
    pconv_kernel<<<dim3(32, 2, BN), 256>>>(cat, 192, 64, WT + OFF_pq3, 64, 128,
                                           nullptr, 0, PQ, 0, 128, 0, 128, 0, nullptr);
    gathermax_kernel<<<dim3(NP / 2, BN), 128>>>(PQ, idxp, cat, 192, 128);

    // ---- global features ----
    pconv_kernel<<<dim3(32, 16, BN), 256>>>(cat, 192, 0, WT + OFF_m1, 192, 1024,
                                            nullptr, 0, nullptr, 0, 0, 0, 1024, 1, pm);
    pmaxreduce_kernel<<<(BN * 1024 + 255) / 256, 256>>>(pm, vec, 1088, 0);
    fc_kernel<<<dim3(BN, 1), 256>>>(l, 16, 16, m2, 16, 64, nullptr, 0, vec, 1088, 1024, 1);
    fc_kernel<<<dim3(BN, 1), 256>>>(vec, 1088, 1088, h1, 1280, 256, nullptr, 0, bsb, 256, 0, 0);

    // ---- head ----
    pconv_kernel<<<dim3(32, 4, BN), 256>>>(cat, 192, 0, WT + OFF_h1p, 192, 256,
                                           bsb, 256, hA, 0, 256, 0, 256, 1, nullptr);
    pconv_kernel<<<dim3(32, 4, BN), 256>>>(hA, 256, 0, WT + OFF_h2, 256, 256,
                                           nullptr, 0, hB, 0, 256, 0, 256, 1, nullptr);
    pconv_kernel<<<dim3(32, 2, BN), 256>>>(hB, 256, 0, WT + OFF_h3, 256, 128,
                                           nullptr, 0, hA, 0, 128, 0, 128, 1, nullptr);
    pconv_kernel<<<dim3(32, 1, BN), 256>>>(hA, 128, 0, WT + OFF_h4, 128, 64,
                                           nullptr, 0, (float*)d_out, 1, 0, 0, 50, 0, nullptr);
}